// round 6
// baseline (speedup 1.0000x reference)
#include <cuda_runtime.h>
#include <cuda_bf16.h>
#include <mma.h>

using namespace nvcuda;

#define BB 16
#define NN 256
#define DM 512
#define HH 8
#define DK 64

// Scratch (allocation-free rule: __device__ globals)
__device__ float g_q[BB*NN*DM];
__device__ float g_k[BB*NN*DM];
__device__ float g_v[BB*NN*DM];
__device__ float g_bias[BB*HH*NN*NN];   // clamped relu(w_g)
__device__ float g_att[BB*NN*DM];       // attention output pre-Wo

__constant__ float c_dim[8] = {
    1.0f, 0.421696503f, 0.177827941f, 0.0749894209f,
    0.0316227766f, 0.0133352143f, 0.00562341325f, 0.00237137371f};

// ---------------------------------------------------------------------------
// BF16 tensor-core GEMM, 3-term precision split:
//   C = Ahi*Bhi + Ahi*Blo + Alo*Bhi   (fp32-class composite accuracy)
// Block tile 128x64, BK=16, 256 threads (8 warps 4x2), warp tile 32x32.
// smem ~16.5KB -> 2 CTAs/SM with grid >= 296.
// ---------------------------------------------------------------------------
struct GemmSmem {
    __nv_bfloat16 Ah[128][24];   // [m][k]
    __nv_bfloat16 Al[128][24];
    __nv_bfloat16 Bh[16][72];    // [k][n]
    __nv_bfloat16 Bl[16][72];
};

#define GM 4096
#define GN 512
#define GK 512

__device__ __forceinline__ void gemm_tile(
    GemmSmem& sm,
    const float* __restrict__ A, const float* __restrict__ W,
    const float* __restrict__ bias, float* __restrict__ C)
{
    const int tid  = threadIdx.x;
    const int warp = tid >> 5;
    const int lane = tid & 31;
    const int wm   = warp >> 1;     // 0..3
    const int wn   = warp & 1;      // 0..1
    const int bm   = blockIdx.y * 128;
    const int bn   = blockIdx.x * 64;

    const int ar = tid >> 1;              // A row 0..127
    const int ac = (tid & 1) * 8;         // A col group (8 floats)
    const int br = tid >> 4;              // B row 0..15
    const int bc = (tid & 15) * 4;        // B col group (4 floats)

    wmma::fragment<wmma::accumulator, 16, 16, 16, float> acc[2][2];
    #pragma unroll
    for (int i = 0; i < 2; i++)
        #pragma unroll
        for (int j = 0; j < 2; j++)
            wmma::fill_fragment(acc[i][j], 0.0f);

    float va[8], vb[4];
    // prologue ldg (k0 = 0)
    {
        const float* ap = &A[(size_t)(bm + ar) * GK + ac];
        float4 f0 = *reinterpret_cast<const float4*>(ap);
        float4 f1 = *reinterpret_cast<const float4*>(ap + 4);
        va[0]=f0.x; va[1]=f0.y; va[2]=f0.z; va[3]=f0.w;
        va[4]=f1.x; va[5]=f1.y; va[6]=f1.z; va[7]=f1.w;
        const float* bp = &W[(size_t)br * GN + bn + bc];
        float4 g0 = *reinterpret_cast<const float4*>(bp);
        vb[0]=g0.x; vb[1]=g0.y; vb[2]=g0.z; vb[3]=g0.w;
    }

    for (int kt = 0; kt < GK / 16; kt++) {
        // stage registers -> smem (bf16 hi + bf16 lo residual)
        #pragma unroll
        for (int i = 0; i < 8; i++) {
            __nv_bfloat16 hi = __float2bfloat16(va[i]);
            sm.Ah[ar][ac + i] = hi;
            sm.Al[ar][ac + i] = __float2bfloat16(va[i] - __bfloat162float(hi));
        }
        #pragma unroll
        for (int i = 0; i < 4; i++) {
            __nv_bfloat16 hi = __float2bfloat16(vb[i]);
            sm.Bh[br][bc + i] = hi;
            sm.Bl[br][bc + i] = __float2bfloat16(vb[i] - __bfloat162float(hi));
        }
        __syncthreads();

        // prefetch next K-slab while mma runs
        if (kt + 1 < GK / 16) {
            const int k0 = (kt + 1) * 16;
            const float* ap = &A[(size_t)(bm + ar) * GK + k0 + ac];
            float4 f0 = *reinterpret_cast<const float4*>(ap);
            float4 f1 = *reinterpret_cast<const float4*>(ap + 4);
            va[0]=f0.x; va[1]=f0.y; va[2]=f0.z; va[3]=f0.w;
            va[4]=f1.x; va[5]=f1.y; va[6]=f1.z; va[7]=f1.w;
            const float* bp = &W[(size_t)(k0 + br) * GN + bn + bc];
            float4 g0 = *reinterpret_cast<const float4*>(bp);
            vb[0]=g0.x; vb[1]=g0.y; vb[2]=g0.z; vb[3]=g0.w;
        }

        // one k16 pass covers BK=16
        {
            wmma::fragment<wmma::matrix_a, 16, 16, 16, __nv_bfloat16,
                           wmma::row_major> ah[2], al[2];
            wmma::fragment<wmma::matrix_b, 16, 16, 16, __nv_bfloat16,
                           wmma::row_major> bh[2], bl[2];
            #pragma unroll
            for (int i = 0; i < 2; i++) {
                wmma::load_matrix_sync(ah[i], &sm.Ah[wm * 32 + i * 16][0], 24);
                wmma::load_matrix_sync(al[i], &sm.Al[wm * 32 + i * 16][0], 24);
            }
            #pragma unroll
            for (int j = 0; j < 2; j++) {
                wmma::load_matrix_sync(bh[j], &sm.Bh[0][wn * 32 + j * 16], 72);
                wmma::load_matrix_sync(bl[j], &sm.Bl[0][wn * 32 + j * 16], 72);
            }
            #pragma unroll
            for (int i = 0; i < 2; i++)
                #pragma unroll
                for (int j = 0; j < 2; j++) {
                    wmma::mma_sync(acc[i][j], ah[i], bh[j], acc[i][j]);
                    wmma::mma_sync(acc[i][j], ah[i], bl[j], acc[i][j]);
                    wmma::mma_sync(acc[i][j], al[i], bh[j], acc[i][j]);
                }
        }
        __syncthreads();
    }

    // epilogue: per-warp fp32 smem scratch (overlays dead tile data), fused bias
    float* epib = reinterpret_cast<float*>(&sm) + warp * 288;  // 16x18 floats
    const int er = lane >> 1;           // row 0..15
    const int ec = (lane & 1) * 8;      // col half
    #pragma unroll
    for (int i = 0; i < 2; i++)
        #pragma unroll
        for (int j = 0; j < 2; j++) {
            wmma::store_matrix_sync(epib, acc[i][j], 18, wmma::mem_row_major);
            __syncwarp();
            const int row = bm + wm * 32 + i * 16 + er;
            const int col = bn + wn * 32 + j * 16 + ec;
            float4 b0 = *reinterpret_cast<const float4*>(&bias[col]);
            float4 b1 = *reinterpret_cast<const float4*>(&bias[col + 4]);
            const float* ep = &epib[er * 18 + ec];
            float4 o0 = {ep[0] + b0.x, ep[1] + b0.y, ep[2] + b0.z, ep[3] + b0.w};
            float4 o1 = {ep[4] + b1.x, ep[5] + b1.y, ep[6] + b1.z, ep[7] + b1.w};
            *reinterpret_cast<float4*>(&C[(size_t)row * GN + col])     = o0;
            *reinterpret_cast<float4*>(&C[(size_t)row * GN + col + 4]) = o1;
            __syncwarp();
        }
}

// Fused Q/K/V projections: blockIdx.z selects the triple. 768 blocks.
__global__ __launch_bounds__(256, 2) void gemm_qkv(
    const float* __restrict__ xq, const float* __restrict__ xk,
    const float* __restrict__ xv,
    const float* __restrict__ Wq, const float* __restrict__ Wk,
    const float* __restrict__ Wv,
    const float* __restrict__ bq, const float* __restrict__ bk,
    const float* __restrict__ bv,
    float* __restrict__ oq, float* __restrict__ ok, float* __restrict__ ov)
{
    __shared__ GemmSmem sm;
    const float *A, *W, *bias;
    float* C;
    if (blockIdx.z == 0)      { A = xq; W = Wq; bias = bq; C = oq; }
    else if (blockIdx.z == 1) { A = xk; W = Wk; bias = bk; C = ok; }
    else                      { A = xv; W = Wv; bias = bv; C = ov; }
    gemm_tile(sm, A, W, bias, C);
}

__global__ __launch_bounds__(256, 2) void gemm_one(
    const float* __restrict__ A, const float* __restrict__ W,
    const float* __restrict__ bias, float* __restrict__ C)
{
    __shared__ GemmSmem sm;
    gemm_tile(sm, A, W, bias, C);
}

// ---------------------------------------------------------------------------
// Geometric weights: block per (q, b), 256 threads = keys.
// Stores clamped relu weight directly (log folded into softmax algebra).
// ---------------------------------------------------------------------------
__global__ __launch_bounds__(256) void geo_bias(
    const float* __restrict__ box, const float* __restrict__ WGw,
    const float* __restrict__ WGb)
{
    __shared__ float sW[HH * 64];
    __shared__ float sB[HH];
    const int b = blockIdx.y;
    const int q = blockIdx.x;
    const int m = threadIdx.x;

    sW[m] = WGw[m];
    sW[m + 256] = WGw[m + 256];
    if (m < HH) sB[m] = WGb[m];
    __syncthreads();

    const float* bq = box + ((size_t)b * NN + q) * 4;
    const float x0q = bq[0], y0q = bq[1], x1q = bq[2], y1q = bq[3];
    const float cxq = (x0q + x1q) * 0.5f, cyq = (y0q + y1q) * 0.5f;
    const float wq = x1q - x0q + 1.0f,   hq = y1q - y0q + 1.0f;

    const float* bmp = box + ((size_t)b * NN + m) * 4;
    const float x0m = bmp[0], y0m = bmp[1], x1m = bmp[2], y1m = bmp[3];
    const float cxm = (x0m + x1m) * 0.5f, cym = (y0m + y1m) * 0.5f;
    const float wm = x1m - x0m + 1.0f,    hm = y1m - y0m + 1.0f;

    float delta[4];
    delta[0] = logf(fmaxf(fabsf((cxq - cxm) / wq), 0.001f));
    delta[1] = logf(fmaxf(fabsf((cyq - cym) / hq), 0.001f));
    delta[2] = logf(wq / wm);
    delta[3] = logf(hq / hm);

    float acc[HH];
    #pragma unroll
    for (int h = 0; h < HH; h++) acc[h] = sB[h];

    #pragma unroll
    for (int p = 0; p < 4; p++) {
        #pragma unroll
        for (int f = 0; f < 8; f++) {
            float ang = 100.0f * delta[p] * c_dim[f];
            float r = ang - 6.28318530717958647692f *
                            rintf(ang * 0.15915494309189533577f);
            float s, c;
            sincosf(r, &s, &c);
            const int idx = p * 8 + f;
            #pragma unroll
            for (int h = 0; h < HH; h++)
                acc[h] += s * sW[h * 64 + idx] + c * sW[h * 64 + 32 + idx];
        }
    }

    #pragma unroll
    for (int h = 0; h < HH; h++) {
        g_bias[(((size_t)b * HH + h) * NN + q) * NN + m] =
            fmaxf(acc[h], 1e-6f);
    }
}

// ---------------------------------------------------------------------------
// Flash-style attention: block per (qtile=64, h, b), 256 threads.
// ---------------------------------------------------------------------------
__global__ __launch_bounds__(256) void attn2(const int* __restrict__ mask)
{
    const int qt = blockIdx.x, h = blockIdx.y, b = blockIdx.z;
    const int qb = qt * 64;
    const int tid = threadIdx.x;

    __shared__ float sQT[64][64];
    __shared__ float sKT[64][32];
    __shared__ float sV [32][64];
    __shared__ float sP [64][32];
    __shared__ float sM[64], sL[64], sScale[64];

    {
        const int q  = tid >> 2;
        const int d0 = (tid & 3) * 16;
        const float* qp = g_q + ((size_t)(b * NN + qb + q)) * DM + h * DK + d0;
        #pragma unroll
        for (int g = 0; g < 4; g++) {
            float4 f = *reinterpret_cast<const float4*>(qp + g * 4);
            sQT[d0 + g*4 + 0][q] = f.x * 0.125f;
            sQT[d0 + g*4 + 1][q] = f.y * 0.125f;
            sQT[d0 + g*4 + 2][q] = f.z * 0.125f;
            sQT[d0 + g*4 + 3][q] = f.w * 0.125f;
        }
    }
    if (tid < 64) { sM[tid] = -3.0e38f; sL[tid] = 0.0f; }

    const int tq = tid >> 4;
    const int tk = tid & 15;
    const int q0 = tq * 4;
    const int k0 = tk * 2;
    const int d0 = tk * 4;
    const int* mk = mask + b * NN;
    const float* wgb = g_bias + ((size_t)(b * HH + h) * NN) * NN;

    float acc[4][4];
    #pragma unroll
    for (int i = 0; i < 4; i++)
        #pragma unroll
        for (int j = 0; j < 4; j++) acc[i][j] = 0.f;

    for (int kt = 0; kt < 8; kt++) {
        const int kg0 = kt * 32;
        __syncthreads();
        {
            const int k  = tid >> 3;
            const int dd = (tid & 7) * 8;
            const float* kp = g_k + ((size_t)(b * NN + kg0 + k)) * DM + h * DK + dd;
            float4 f0 = *reinterpret_cast<const float4*>(kp);
            float4 f1 = *reinterpret_cast<const float4*>(kp + 4);
            sKT[dd + 0][k] = f0.x; sKT[dd + 1][k] = f0.y;
            sKT[dd + 2][k] = f0.z; sKT[dd + 3][k] = f0.w;
            sKT[dd + 4][k] = f1.x; sKT[dd + 5][k] = f1.y;
            sKT[dd + 6][k] = f1.z; sKT[dd + 7][k] = f1.w;
            const float* vp = g_v + ((size_t)(b * NN + kg0 + k)) * DM + h * DK + dd;
            *reinterpret_cast<float4*>(&sV[k][dd])     =
                *reinterpret_cast<const float4*>(vp);
            *reinterpret_cast<float4*>(&sV[k][dd + 4]) =
                *reinterpret_cast<const float4*>(vp + 4);
        }
        __syncthreads();

        float s00=0,s01=0,s10=0,s11=0,s20=0,s21=0,s30=0,s31=0;
        #pragma unroll 8
        for (int d = 0; d < 64; d++) {
            float4 qa = *reinterpret_cast<const float4*>(&sQT[d][q0]);
            float2 kb = *reinterpret_cast<const float2*>(&sKT[d][k0]);
            s00 += qa.x * kb.x; s01 += qa.x * kb.y;
            s10 += qa.y * kb.x; s11 += qa.y * kb.y;
            s20 += qa.z * kb.x; s21 += qa.z * kb.y;
            s30 += qa.w * kb.x; s31 += qa.w * kb.y;
        }
        float s[4][2] = {{s00,s01},{s10,s11},{s20,s21},{s30,s31}};

        const int km0 = kg0 + k0, km1 = km0 + 1;
        const bool m0 = (mk[km0] == 0), m1 = (mk[km1] == 0);
        float mt[4];
        #pragma unroll
        for (int qi = 0; qi < 4; qi++) {
            if (m0) s[qi][0] = -1e9f;
            if (m1) s[qi][1] = -1e9f;
            mt[qi] = fmaxf(s[qi][0], s[qi][1]);
            #pragma unroll
            for (int o = 1; o < 16; o <<= 1)
                mt[qi] = fmaxf(mt[qi], __shfl_xor_sync(0xffffffffu, mt[qi], o));
        }
        if (tk == 0) {
            #pragma unroll
            for (int qi = 0; qi < 4; qi++) {
                const int q = q0 + qi;
                float m_old = sM[q];
                float m_new = fmaxf(m_old, mt[qi]);
                sM[q] = m_new;
                float scv = __expf(m_old - m_new);
                sScale[q] = scv;
                sL[q] *= scv;
            }
        }
        __syncthreads();

        float sums[4];
        #pragma unroll
        for (int qi = 0; qi < 4; qi++) {
            const int q = q0 + qi;
            const float mq = sM[q];
            float2 wg = *reinterpret_cast<const float2*>(
                &wgb[(size_t)(qb + q) * NN + km0]);
            float p0 = wg.x * __expf(s[qi][0] - mq);
            float p1 = wg.y * __expf(s[qi][1] - mq);
            sP[q][k0]     = p0;
            sP[q][k0 + 1] = p1;
            float su = p0 + p1;
            #pragma unroll
            for (int o = 1; o < 16; o <<= 1)
                su += __shfl_xor_sync(0xffffffffu, su, o);
            sums[qi] = su;
        }
        if (tk == 0) {
            #pragma unroll
            for (int qi = 0; qi < 4; qi++) sL[q0 + qi] += sums[qi];
        }
        __syncthreads();

        float sc4[4];
        #pragma unroll
        for (int qi = 0; qi < 4; qi++) sc4[qi] = sScale[q0 + qi];
        #pragma unroll
        for (int qi = 0; qi < 4; qi++)
            #pragma unroll
            for (int dj = 0; dj < 4; dj++) acc[qi][dj] *= sc4[qi];
        #pragma unroll 4
        for (int k = 0; k < 32; k++) {
            float4 v4 = *reinterpret_cast<const float4*>(&sV[k][d0]);
            float p0 = sP[q0 + 0][k];
            float p1 = sP[q0 + 1][k];
            float p2 = sP[q0 + 2][k];
            float p3 = sP[q0 + 3][k];
            acc[0][0] += p0 * v4.x; acc[0][1] += p0 * v4.y;
            acc[0][2] += p0 * v4.z; acc[0][3] += p0 * v4.w;
            acc[1][0] += p1 * v4.x; acc[1][1] += p1 * v4.y;
            acc[1][2] += p1 * v4.z; acc[1][3] += p1 * v4.w;
            acc[2][0] += p2 * v4.x; acc[2][1] += p2 * v4.y;
            acc[2][2] += p2 * v4.z; acc[2][3] += p2 * v4.w;
            acc[3][0] += p3 * v4.x; acc[3][1] += p3 * v4.y;
            acc[3][2] += p3 * v4.z; acc[3][3] += p3 * v4.w;
        }
    }

    #pragma unroll
    for (int qi = 0; qi < 4; qi++) {
        const int q = q0 + qi;
        const float inv = 1.0f / sL[q];
        float4 o;
        o.x = acc[qi][0] * inv; o.y = acc[qi][1] * inv;
        o.z = acc[qi][2] * inv; o.w = acc[qi][3] * inv;
        *reinterpret_cast<float4*>(
            &g_att[((size_t)(b * NN + qb + q)) * DM + h * DK + d0]) = o;
    }
}

// ---------------------------------------------------------------------------
extern "C" void kernel_launch(void* const* d_in, const int* in_sizes, int n_in,
                              void* d_out, int out_size)
{
    const float* xq  = (const float*)d_in[0];
    const float* xk  = (const float*)d_in[1];
    const float* xv  = (const float*)d_in[2];
    const float* box = (const float*)d_in[3];
    const int*   msk = (const int*)  d_in[4];
    const float* Wq  = (const float*)d_in[5];
    const float* bq  = (const float*)d_in[6];
    const float* Wk  = (const float*)d_in[7];
    const float* bk  = (const float*)d_in[8];
    const float* Wv  = (const float*)d_in[9];
    const float* bv  = (const float*)d_in[10];
    const float* Wo  = (const float*)d_in[11];
    const float* bo  = (const float*)d_in[12];
    const float* WGw = (const float*)d_in[13];
    const float* WGb = (const float*)d_in[14];

    float* out = (float*)d_out;

    void *pq, *pk, *pv, *pa;
    cudaGetSymbolAddress(&pq, g_q);
    cudaGetSymbolAddress(&pk, g_k);
    cudaGetSymbolAddress(&pv, g_v);
    cudaGetSymbolAddress(&pa, g_att);

    // side stream + events for geo ‖ QKV overlap (created once; host-side
    // resources only — no device memory). Capture-safe fork/join pattern.
    static cudaStream_t s_geo = nullptr;
    static cudaEvent_t  e_fork = nullptr, e_join = nullptr;
    if (s_geo == nullptr) {
        cudaStreamCreateWithFlags(&s_geo, cudaStreamNonBlocking);
        cudaEventCreateWithFlags(&e_fork, cudaEventDisableTiming);
        cudaEventCreateWithFlags(&e_join, cudaEventDisableTiming);
    }

    dim3 qkvgrid(GN / 64, GM / 128, 3);     // (8, 32, 3) = 768 blocks
    dim3 ogrid  (GN / 64, GM / 128);        // (8, 32)    = 256 blocks

    // fork: geo_bias runs concurrently with the QKV projections
    cudaEventRecord(e_fork, 0);
    cudaStreamWaitEvent(s_geo, e_fork, 0);
    geo_bias<<<dim3(NN, BB), 256, 0, s_geo>>>(box, WGw, WGb);
    cudaEventRecord(e_join, s_geo);

    gemm_qkv<<<qkvgrid, 256>>>(xq, xk, xv, Wq, Wk, Wv, bq, bk, bv,
                               (float*)pq, (float*)pk, (float*)pv);

    // join: attention needs both QKV and geo weights
    cudaStreamWaitEvent(0, e_join, 0);

    attn2<<<dim3(NN / 64, HH, BB), 256>>>(msk);

    gemm_one<<<ogrid, 256>>>((const float*)pa, Wo, bo, out);
}

// round 8
// speedup vs baseline: 1.0359x; 1.0359x over previous
#include <cuda_runtime.h>
#include <cuda_bf16.h>
#include <mma.h>

using namespace nvcuda;

#define BB 16
#define NN 256
#define DM 512
#define HH 8
#define DK 64

// Scratch (allocation-free rule: __device__ globals)
__device__ float g_q[BB*NN*DM];
__device__ float g_k[BB*NN*DM];
__device__ float g_v[BB*NN*DM];
__device__ float g_bias[BB*HH*NN*NN];   // clamped relu(w_g)
__device__ float g_att[BB*NN*DM];       // attention output pre-Wo

__constant__ float c_dim[8] = {
    1.0f, 0.421696503f, 0.177827941f, 0.0749894209f,
    0.0316227766f, 0.0133352143f, 0.00562341325f, 0.00237137371f};

// ---------------------------------------------------------------------------
// BF16 tensor-core GEMM, 3-term precision split (R5 config — best measured):
//   C = Ahi*Bhi + Ahi*Blo + Alo*Bhi
// Block tile 128x128, BK=16, 256 threads (8 warps 2x4), warp tile 64x32.
// ---------------------------------------------------------------------------
struct GemmSmem {
    __nv_bfloat16 Ah[128][24];   // [m][k]
    __nv_bfloat16 Al[128][24];
    __nv_bfloat16 Bh[16][136];   // [k][n]
    __nv_bfloat16 Bl[16][136];
};

#define GM 4096
#define GN 512
#define GK 512

__device__ __forceinline__ void gemm_tile(
    GemmSmem& sm,
    const float* __restrict__ A, const float* __restrict__ W,
    const float* __restrict__ bias, float* __restrict__ C)
{
    const int tid  = threadIdx.x;
    const int warp = tid >> 5;
    const int lane = tid & 31;
    const int wm   = warp >> 2;     // 0..1
    const int wn   = warp & 3;      // 0..3
    const int bm   = blockIdx.y * 128;
    const int bn   = blockIdx.x * 128;

    const int ar = tid >> 1;              // A row 0..127
    const int ac = (tid & 1) * 8;         // A col group
    const int br = tid >> 4;              // B row 0..15
    const int bc = (tid & 15) * 8;        // B col group

    wmma::fragment<wmma::accumulator, 16, 16, 16, float> acc[4][2];
    #pragma unroll
    for (int i = 0; i < 4; i++)
        #pragma unroll
        for (int j = 0; j < 2; j++)
            wmma::fill_fragment(acc[i][j], 0.0f);

    float va[8], vb[8];
    // prologue ldg (k0 = 0)
    {
        const float* ap = &A[(size_t)(bm + ar) * GK + ac];
        float4 f0 = *reinterpret_cast<const float4*>(ap);
        float4 f1 = *reinterpret_cast<const float4*>(ap + 4);
        va[0]=f0.x; va[1]=f0.y; va[2]=f0.z; va[3]=f0.w;
        va[4]=f1.x; va[5]=f1.y; va[6]=f1.z; va[7]=f1.w;
        const float* bp = &W[(size_t)br * GN + bn + bc];
        float4 g0 = *reinterpret_cast<const float4*>(bp);
        float4 g1 = *reinterpret_cast<const float4*>(bp + 4);
        vb[0]=g0.x; vb[1]=g0.y; vb[2]=g0.z; vb[3]=g0.w;
        vb[4]=g1.x; vb[5]=g1.y; vb[6]=g1.z; vb[7]=g1.w;
    }

    for (int kt = 0; kt < GK / 16; kt++) {
        // stage registers -> smem (bf16 hi + bf16 lo residual)
        #pragma unroll
        for (int i = 0; i < 8; i++) {
            __nv_bfloat16 hi = __float2bfloat16(va[i]);
            sm.Ah[ar][ac + i] = hi;
            sm.Al[ar][ac + i] = __float2bfloat16(va[i] - __bfloat162float(hi));
        }
        #pragma unroll
        for (int i = 0; i < 8; i++) {
            __nv_bfloat16 hi = __float2bfloat16(vb[i]);
            sm.Bh[br][bc + i] = hi;
            sm.Bl[br][bc + i] = __float2bfloat16(vb[i] - __bfloat162float(hi));
        }
        __syncthreads();

        // prefetch next K-slab while mma runs
        if (kt + 1 < GK / 16) {
            const int k0 = (kt + 1) * 16;
            const float* ap = &A[(size_t)(bm + ar) * GK + k0 + ac];
            float4 f0 = *reinterpret_cast<const float4*>(ap);
            float4 f1 = *reinterpret_cast<const float4*>(ap + 4);
            va[0]=f0.x; va[1]=f0.y; va[2]=f0.z; va[3]=f0.w;
            va[4]=f1.x; va[5]=f1.y; va[6]=f1.z; va[7]=f1.w;
            const float* bp = &W[(size_t)(k0 + br) * GN + bn + bc];
            float4 g0 = *reinterpret_cast<const float4*>(bp);
            float4 g1 = *reinterpret_cast<const float4*>(bp + 4);
            vb[0]=g0.x; vb[1]=g0.y; vb[2]=g0.z; vb[3]=g0.w;
            vb[4]=g1.x; vb[5]=g1.y; vb[6]=g1.z; vb[7]=g1.w;
        }

        // one k16 pass covers BK=16
        {
            wmma::fragment<wmma::matrix_a, 16, 16, 16, __nv_bfloat16,
                           wmma::row_major> ah[4], al[4];
            wmma::fragment<wmma::matrix_b, 16, 16, 16, __nv_bfloat16,
                           wmma::row_major> bh[2], bl[2];
            #pragma unroll
            for (int i = 0; i < 4; i++) {
                wmma::load_matrix_sync(ah[i], &sm.Ah[wm * 64 + i * 16][0], 24);
                wmma::load_matrix_sync(al[i], &sm.Al[wm * 64 + i * 16][0], 24);
            }
            #pragma unroll
            for (int j = 0; j < 2; j++) {
                wmma::load_matrix_sync(bh[j], &sm.Bh[0][wn * 32 + j * 16], 136);
                wmma::load_matrix_sync(bl[j], &sm.Bl[0][wn * 32 + j * 16], 136);
            }
            #pragma unroll
            for (int i = 0; i < 4; i++)
                #pragma unroll
                for (int j = 0; j < 2; j++) {
                    wmma::mma_sync(acc[i][j], ah[i], bh[j], acc[i][j]);
                    wmma::mma_sync(acc[i][j], ah[i], bl[j], acc[i][j]);
                    wmma::mma_sync(acc[i][j], al[i], bh[j], acc[i][j]);
                }
        }
        __syncthreads();
    }

    // epilogue: per-warp fp32 smem scratch (overlays dead tile data), fused bias
    float* epib = reinterpret_cast<float*>(&sm) + warp * 288;  // 16x18 floats
    const int er = lane >> 1;           // row 0..15
    const int ec = (lane & 1) * 8;      // col half
    #pragma unroll
    for (int i = 0; i < 4; i++)
        #pragma unroll
        for (int j = 0; j < 2; j++) {
            wmma::store_matrix_sync(epib, acc[i][j], 18, wmma::mem_row_major);
            __syncwarp();
            const int row = bm + wm * 64 + i * 16 + er;
            const int col = bn + wn * 32 + j * 16 + ec;
            float4 b0 = *reinterpret_cast<const float4*>(&bias[col]);
            float4 b1 = *reinterpret_cast<const float4*>(&bias[col + 4]);
            const float* ep = &epib[er * 18 + ec];
            float4 o0 = {ep[0] + b0.x, ep[1] + b0.y, ep[2] + b0.z, ep[3] + b0.w};
            float4 o1 = {ep[4] + b1.x, ep[5] + b1.y, ep[6] + b1.z, ep[7] + b1.w};
            *reinterpret_cast<float4*>(&C[(size_t)row * GN + col])     = o0;
            *reinterpret_cast<float4*>(&C[(size_t)row * GN + col + 4]) = o1;
            __syncwarp();
        }
}

// Fused Q/K/V projections: blockIdx.z selects the triple. 384 blocks.
__global__ __launch_bounds__(256, 2) void gemm_qkv(
    const float* __restrict__ xq, const float* __restrict__ xk,
    const float* __restrict__ xv,
    const float* __restrict__ Wq, const float* __restrict__ Wk,
    const float* __restrict__ Wv,
    const float* __restrict__ bq, const float* __restrict__ bk,
    const float* __restrict__ bv,
    float* __restrict__ oq, float* __restrict__ ok, float* __restrict__ ov)
{
    __shared__ GemmSmem sm;
    const float *A, *W, *bias;
    float* C;
    if (blockIdx.z == 0)      { A = xq; W = Wq; bias = bq; C = oq; }
    else if (blockIdx.z == 1) { A = xk; W = Wk; bias = bk; C = ok; }
    else                      { A = xv; W = Wv; bias = bv; C = ov; }
    gemm_tile(sm, A, W, bias, C);
}

__global__ __launch_bounds__(256, 2) void gemm_one(
    const float* __restrict__ A, const float* __restrict__ W,
    const float* __restrict__ bias, float* __restrict__ C)
{
    __shared__ GemmSmem sm;
    gemm_tile(sm, A, W, bias, C);
}

// ---------------------------------------------------------------------------
// Geometric weights: block per (q, b), 256 threads = keys.
// Stores clamped relu weight directly (log folded into softmax algebra).
// ---------------------------------------------------------------------------
__global__ __launch_bounds__(256) void geo_bias(
    const float* __restrict__ box, const float* __restrict__ WGw,
    const float* __restrict__ WGb)
{
    __shared__ float sW[HH * 64];
    __shared__ float sB[HH];
    const int b = blockIdx.y;
    const int q = blockIdx.x;
    const int m = threadIdx.x;

    sW[m] = WGw[m];
    sW[m + 256] = WGw[m + 256];
    if (m < HH) sB[m] = WGb[m];
    __syncthreads();

    const float* bq = box + ((size_t)b * NN + q) * 4;
    const float x0q = bq[0], y0q = bq[1], x1q = bq[2], y1q = bq[3];
    const float cxq = (x0q + x1q) * 0.5f, cyq = (y0q + y1q) * 0.5f;
    const float wq = x1q - x0q + 1.0f,   hq = y1q - y0q + 1.0f;

    const float* bmp = box + ((size_t)b * NN + m) * 4;
    const float x0m = bmp[0], y0m = bmp[1], x1m = bmp[2], y1m = bmp[3];
    const float cxm = (x0m + x1m) * 0.5f, cym = (y0m + y1m) * 0.5f;
    const float wm = x1m - x0m + 1.0f,    hm = y1m - y0m + 1.0f;

    float delta[4];
    delta[0] = logf(fmaxf(fabsf((cxq - cxm) / wq), 0.001f));
    delta[1] = logf(fmaxf(fabsf((cyq - cym) / hq), 0.001f));
    delta[2] = logf(wq / wm);
    delta[3] = logf(hq / hm);

    float acc[HH];
    #pragma unroll
    for (int h = 0; h < HH; h++) acc[h] = sB[h];

    #pragma unroll
    for (int p = 0; p < 4; p++) {
        #pragma unroll
        for (int f = 0; f < 8; f++) {
            float ang = 100.0f * delta[p] * c_dim[f];
            float r = ang - 6.28318530717958647692f *
                            rintf(ang * 0.15915494309189533577f);
            float s, c;
            sincosf(r, &s, &c);
            const int idx = p * 8 + f;
            #pragma unroll
            for (int h = 0; h < HH; h++)
                acc[h] += s * sW[h * 64 + idx] + c * sW[h * 64 + 32 + idx];
        }
    }

    #pragma unroll
    for (int h = 0; h < HH; h++) {
        g_bias[(((size_t)b * HH + h) * NN + q) * NN + m] =
            fmaxf(acc[h], 1e-6f);
    }
}

// ---------------------------------------------------------------------------
// Flash-style attention: block per (qtile=64, h, b), 256 threads.
// ---------------------------------------------------------------------------
__global__ __launch_bounds__(256) void attn2(const int* __restrict__ mask)
{
    const int qt = blockIdx.x, h = blockIdx.y, b = blockIdx.z;
    const int qb = qt * 64;
    const int tid = threadIdx.x;

    __shared__ float sQT[64][64];
    __shared__ float sKT[64][32];
    __shared__ float sV [32][64];
    __shared__ float sP [64][32];
    __shared__ float sM[64], sL[64], sScale[64];

    {
        const int q  = tid >> 2;
        const int d0 = (tid & 3) * 16;
        const float* qp = g_q + ((size_t)(b * NN + qb + q)) * DM + h * DK + d0;
        #pragma unroll
        for (int g = 0; g < 4; g++) {
            float4 f = *reinterpret_cast<const float4*>(qp + g * 4);
            sQT[d0 + g*4 + 0][q] = f.x * 0.125f;
            sQT[d0 + g*4 + 1][q] = f.y * 0.125f;
            sQT[d0 + g*4 + 2][q] = f.z * 0.125f;
            sQT[d0 + g*4 + 3][q] = f.w * 0.125f;
        }
    }
    if (tid < 64) { sM[tid] = -3.0e38f; sL[tid] = 0.0f; }

    const int tq = tid >> 4;
    const int tk = tid & 15;
    const int q0 = tq * 4;
    const int k0 = tk * 2;
    const int d0 = tk * 4;
    const int* mk = mask + b * NN;
    const float* wgb = g_bias + ((size_t)(b * HH + h) * NN) * NN;

    float acc[4][4];
    #pragma unroll
    for (int i = 0; i < 4; i++)
        #pragma unroll
        for (int j = 0; j < 4; j++) acc[i][j] = 0.f;

    for (int kt = 0; kt < 8; kt++) {
        const int kg0 = kt * 32;
        __syncthreads();
        {
            const int k  = tid >> 3;
            const int dd = (tid & 7) * 8;
            const float* kp = g_k + ((size_t)(b * NN + kg0 + k)) * DM + h * DK + dd;
            float4 f0 = *reinterpret_cast<const float4*>(kp);
            float4 f1 = *reinterpret_cast<const float4*>(kp + 4);
            sKT[dd + 0][k] = f0.x; sKT[dd + 1][k] = f0.y;
            sKT[dd + 2][k] = f0.z; sKT[dd + 3][k] = f0.w;
            sKT[dd + 4][k] = f1.x; sKT[dd + 5][k] = f1.y;
            sKT[dd + 6][k] = f1.z; sKT[dd + 7][k] = f1.w;
            const float* vp = g_v + ((size_t)(b * NN + kg0 + k)) * DM + h * DK + dd;
            *reinterpret_cast<float4*>(&sV[k][dd])     =
                *reinterpret_cast<const float4*>(vp);
            *reinterpret_cast<float4*>(&sV[k][dd + 4]) =
                *reinterpret_cast<const float4*>(vp + 4);
        }
        __syncthreads();

        float s00=0,s01=0,s10=0,s11=0,s20=0,s21=0,s30=0,s31=0;
        #pragma unroll 8
        for (int d = 0; d < 64; d++) {
            float4 qa = *reinterpret_cast<const float4*>(&sQT[d][q0]);
            float2 kb = *reinterpret_cast<const float2*>(&sKT[d][k0]);
            s00 += qa.x * kb.x; s01 += qa.x * kb.y;
            s10 += qa.y * kb.x; s11 += qa.y * kb.y;
            s20 += qa.z * kb.x; s21 += qa.z * kb.y;
            s30 += qa.w * kb.x; s31 += qa.w * kb.y;
        }
        float s[4][2] = {{s00,s01},{s10,s11},{s20,s21},{s30,s31}};

        const int km0 = kg0 + k0, km1 = km0 + 1;
        const bool m0 = (mk[km0] == 0), m1 = (mk[km1] == 0);
        float mt[4];
        #pragma unroll
        for (int qi = 0; qi < 4; qi++) {
            if (m0) s[qi][0] = -1e9f;
            if (m1) s[qi][1] = -1e9f;
            mt[qi] = fmaxf(s[qi][0], s[qi][1]);
            #pragma unroll
            for (int o = 1; o < 16; o <<= 1)
                mt[qi] = fmaxf(mt[qi], __shfl_xor_sync(0xffffffffu, mt[qi], o));
        }
        if (tk == 0) {
            #pragma unroll
            for (int qi = 0; qi < 4; qi++) {
                const int q = q0 + qi;
                float m_old = sM[q];
                float m_new = fmaxf(m_old, mt[qi]);
                sM[q] = m_new;
                float scv = __expf(m_old - m_new);
                sScale[q] = scv;
                sL[q] *= scv;
            }
        }
        __syncthreads();

        float sums[4];
        #pragma unroll
        for (int qi = 0; qi < 4; qi++) {
            const int q = q0 + qi;
            const float mq = sM[q];
            float2 wg = *reinterpret_cast<const float2*>(
                &wgb[(size_t)(qb + q) * NN + km0]);
            float p0 = wg.x * __expf(s[qi][0] - mq);
            float p1 = wg.y * __expf(s[qi][1] - mq);
            sP[q][k0]     = p0;
            sP[q][k0 + 1] = p1;
            float su = p0 + p1;
            #pragma unroll
            for (int o = 1; o < 16; o <<= 1)
                su += __shfl_xor_sync(0xffffffffu, su, o);
            sums[qi] = su;
        }
        if (tk == 0) {
            #pragma unroll
            for (int qi = 0; qi < 4; qi++) sL[q0 + qi] += sums[qi];
        }
        __syncthreads();

        float sc4[4];
        #pragma unroll
        for (int qi = 0; qi < 4; qi++) sc4[qi] = sScale[q0 + qi];
        #pragma unroll
        for (int qi = 0; qi < 4; qi++)
            #pragma unroll
            for (int dj = 0; dj < 4; dj++) acc[qi][dj] *= sc4[qi];
        #pragma unroll 4
        for (int k = 0; k < 32; k++) {
            float4 v4 = *reinterpret_cast<const float4*>(&sV[k][d0]);
            float p0 = sP[q0 + 0][k];
            float p1 = sP[q0 + 1][k];
            float p2 = sP[q0 + 2][k];
            float p3 = sP[q0 + 3][k];
            acc[0][0] += p0 * v4.x; acc[0][1] += p0 * v4.y;
            acc[0][2] += p0 * v4.z; acc[0][3] += p0 * v4.w;
            acc[1][0] += p1 * v4.x; acc[1][1] += p1 * v4.y;
            acc[1][2] += p1 * v4.z; acc[1][3] += p1 * v4.w;
            acc[2][0] += p2 * v4.x; acc[2][1] += p2 * v4.y;
            acc[2][2] += p2 * v4.z; acc[2][3] += p2 * v4.w;
            acc[3][0] += p3 * v4.x; acc[3][1] += p3 * v4.y;
            acc[3][2] += p3 * v4.z; acc[3][3] += p3 * v4.w;
        }
    }

    #pragma unroll
    for (int qi = 0; qi < 4; qi++) {
        const int q = q0 + qi;
        const float inv = 1.0f / sL[q];
        float4 o;
        o.x = acc[qi][0] * inv; o.y = acc[qi][1] * inv;
        o.z = acc[qi][2] * inv; o.w = acc[qi][3] * inv;
        *reinterpret_cast<float4*>(
            &g_att[((size_t)(b * NN + qb + q)) * DM + h * DK + d0]) = o;
    }
}

// ---------------------------------------------------------------------------
extern "C" void kernel_launch(void* const* d_in, const int* in_sizes, int n_in,
                              void* d_out, int out_size)
{
    const float* xq  = (const float*)d_in[0];
    const float* xk  = (const float*)d_in[1];
    const float* xv  = (const float*)d_in[2];
    const float* box = (const float*)d_in[3];
    const int*   msk = (const int*)  d_in[4];
    const float* Wq  = (const float*)d_in[5];
    const float* bq  = (const float*)d_in[6];
    const float* Wk  = (const float*)d_in[7];
    const float* bk  = (const float*)d_in[8];
    const float* Wv  = (const float*)d_in[9];
    const float* bv  = (const float*)d_in[10];
    const float* Wo  = (const float*)d_in[11];
    const float* bo  = (const float*)d_in[12];
    const float* WGw = (const float*)d_in[13];
    const float* WGb = (const float*)d_in[14];

    float* out = (float*)d_out;

    void *pq, *pk, *pv, *pa;
    cudaGetSymbolAddress(&pq, g_q);
    cudaGetSymbolAddress(&pk, g_k);
    cudaGetSymbolAddress(&pv, g_v);
    cudaGetSymbolAddress(&pa, g_att);

    // side stream + events for geo ‖ QKV overlap (host-side resources only;
    // capture-safe fork/join pattern)
    static cudaStream_t s_geo = nullptr;
    static cudaEvent_t  e_fork = nullptr, e_join = nullptr;
    if (s_geo == nullptr) {
        cudaStreamCreateWithFlags(&s_geo, cudaStreamNonBlocking);
        cudaEventCreateWithFlags(&e_fork, cudaEventDisableTiming);
        cudaEventCreateWithFlags(&e_join, cudaEventDisableTiming);
    }

    dim3 qkvgrid(GN / 128, GM / 128, 3);    // (4, 32, 3) = 384 blocks
    dim3 ogrid  (GN / 128, GM / 128);       // (4, 32)    = 128 blocks

    // fork: geo_bias runs concurrently with the QKV projections
    cudaEventRecord(e_fork, 0);
    cudaStreamWaitEvent(s_geo, e_fork, 0);
    geo_bias<<<dim3(NN, BB), 256, 0, s_geo>>>(box, WGw, WGb);
    cudaEventRecord(e_join, s_geo);

    gemm_qkv<<<qkvgrid, 256>>>(xq, xk, xv, Wq, Wk, Wv, bq, bk, bv,
                               (float*)pq, (float*)pk, (float*)pv);

    // join: attention needs both QKV and geo weights
    cudaStreamWaitEvent(0, e_join, 0);

    attn2<<<dim3(NN / 64, HH, BB), 256>>>(msk);

    gemm_one<<<ogrid, 256>>>((const float*)pa, Wo, bo, out);
}

// round 9
// speedup vs baseline: 1.0607x; 1.0240x over previous
#include <cuda_runtime.h>
#include <cuda_bf16.h>
#include <mma.h>

using namespace nvcuda;

#define BB 16
#define NN 256
#define DM 512
#define HH 8
#define DK 64

// Scratch (allocation-free rule: __device__ globals)
__device__ float g_q[BB*NN*DM];
__device__ float g_k[BB*NN*DM];
__device__ float g_v[BB*NN*DM];
__device__ float g_bias[BB*HH*NN*NN];   // clamped relu(w_g)
__device__ float g_att[BB*NN*DM];       // attention output pre-Wo

__constant__ float c_dim[8] = {
    1.0f, 0.421696503f, 0.177827941f, 0.0749894209f,
    0.0316227766f, 0.0133352143f, 0.00562341325f, 0.00237137371f};

// ---------------------------------------------------------------------------
// BF16 tensor-core GEMM, 3-term precision split, DOUBLE-BUFFERED smem:
//   C = Ahi*Bhi + Ahi*Blo + Alo*Bhi
// Block tile 128x128, BK=16, 256 threads (8 warps 2x4), warp tile 64x32.
// Per iteration: ldg(next) -> mma(cur) -> stage(next) -> ONE sync.
// ---------------------------------------------------------------------------
struct GemmSmem {
    __nv_bfloat16 Ah[128][24];   // [m][k]
    __nv_bfloat16 Al[128][24];
    __nv_bfloat16 Bh[16][136];   // [k][n]
    __nv_bfloat16 Bl[16][136];
};

#define GM 4096
#define GN 512
#define GK 512
#define NKT (GK / 16)   // 32

__device__ __forceinline__ void stage_to(
    GemmSmem& sm, const float* va, const float* vb, int ar, int ac, int br, int bc)
{
    #pragma unroll
    for (int i = 0; i < 8; i++) {
        __nv_bfloat16 hi = __float2bfloat16(va[i]);
        sm.Ah[ar][ac + i] = hi;
        sm.Al[ar][ac + i] = __float2bfloat16(va[i] - __bfloat162float(hi));
    }
    #pragma unroll
    for (int i = 0; i < 8; i++) {
        __nv_bfloat16 hi = __float2bfloat16(vb[i]);
        sm.Bh[br][bc + i] = hi;
        sm.Bl[br][bc + i] = __float2bfloat16(vb[i] - __bfloat162float(hi));
    }
}

__device__ __forceinline__ void gemm_tile(
    GemmSmem* sm,   // [2]
    const float* __restrict__ A, const float* __restrict__ W,
    const float* __restrict__ bias, float* __restrict__ C)
{
    const int tid  = threadIdx.x;
    const int warp = tid >> 5;
    const int lane = tid & 31;
    const int wm   = warp >> 2;     // 0..1
    const int wn   = warp & 3;      // 0..3
    const int bm   = blockIdx.y * 128;
    const int bn   = blockIdx.x * 128;

    const int ar = tid >> 1;              // A row 0..127
    const int ac = (tid & 1) * 8;         // A col group
    const int br = tid >> 4;              // B row 0..15
    const int bc = (tid & 15) * 8;        // B col group

    wmma::fragment<wmma::accumulator, 16, 16, 16, float> acc[4][2];
    #pragma unroll
    for (int i = 0; i < 4; i++)
        #pragma unroll
        for (int j = 0; j < 2; j++)
            wmma::fill_fragment(acc[i][j], 0.0f);

    float va[8], vb[8];
    // prologue: ldg k-slab 0 and stage into buffer 0
    {
        const float* ap = &A[(size_t)(bm + ar) * GK + ac];
        float4 f0 = *reinterpret_cast<const float4*>(ap);
        float4 f1 = *reinterpret_cast<const float4*>(ap + 4);
        va[0]=f0.x; va[1]=f0.y; va[2]=f0.z; va[3]=f0.w;
        va[4]=f1.x; va[5]=f1.y; va[6]=f1.z; va[7]=f1.w;
        const float* bp = &W[(size_t)br * GN + bn + bc];
        float4 g0 = *reinterpret_cast<const float4*>(bp);
        float4 g1 = *reinterpret_cast<const float4*>(bp + 4);
        vb[0]=g0.x; vb[1]=g0.y; vb[2]=g0.z; vb[3]=g0.w;
        vb[4]=g1.x; vb[5]=g1.y; vb[6]=g1.z; vb[7]=g1.w;
        stage_to(sm[0], va, vb, ar, ac, br, bc);
    }
    __syncthreads();

    for (int kt = 0; kt < NKT; kt++) {
        const int cur = kt & 1;
        const bool more = (kt + 1 < NKT);

        // ldg next k-slab (latency hidden by mma below)
        if (more) {
            const int k0 = (kt + 1) * 16;
            const float* ap = &A[(size_t)(bm + ar) * GK + k0 + ac];
            float4 f0 = *reinterpret_cast<const float4*>(ap);
            float4 f1 = *reinterpret_cast<const float4*>(ap + 4);
            va[0]=f0.x; va[1]=f0.y; va[2]=f0.z; va[3]=f0.w;
            va[4]=f1.x; va[5]=f1.y; va[6]=f1.z; va[7]=f1.w;
            const float* bp = &W[(size_t)(k0 + br) * GN + bn + bc];
            float4 g0 = *reinterpret_cast<const float4*>(bp);
            float4 g1 = *reinterpret_cast<const float4*>(bp + 4);
            vb[0]=g0.x; vb[1]=g0.y; vb[2]=g0.z; vb[3]=g0.w;
            vb[4]=g1.x; vb[5]=g1.y; vb[6]=g1.z; vb[7]=g1.w;
        }

        // mma on current buffer
        {
            GemmSmem& s = sm[cur];
            wmma::fragment<wmma::matrix_a, 16, 16, 16, __nv_bfloat16,
                           wmma::row_major> ah[4], al[4];
            wmma::fragment<wmma::matrix_b, 16, 16, 16, __nv_bfloat16,
                           wmma::row_major> bh[2], bl[2];
            #pragma unroll
            for (int i = 0; i < 4; i++) {
                wmma::load_matrix_sync(ah[i], &s.Ah[wm * 64 + i * 16][0], 24);
                wmma::load_matrix_sync(al[i], &s.Al[wm * 64 + i * 16][0], 24);
            }
            #pragma unroll
            for (int j = 0; j < 2; j++) {
                wmma::load_matrix_sync(bh[j], &s.Bh[0][wn * 32 + j * 16], 136);
                wmma::load_matrix_sync(bl[j], &s.Bl[0][wn * 32 + j * 16], 136);
            }
            #pragma unroll
            for (int i = 0; i < 4; i++)
                #pragma unroll
                for (int j = 0; j < 2; j++) {
                    wmma::mma_sync(acc[i][j], ah[i], bh[j], acc[i][j]);
                    wmma::mma_sync(acc[i][j], ah[i], bl[j], acc[i][j]);
                    wmma::mma_sync(acc[i][j], al[i], bh[j], acc[i][j]);
                }
        }

        // stage next slab into the other buffer (overlaps with mma in flight)
        if (more)
            stage_to(sm[cur ^ 1], va, vb, ar, ac, br, bc);
        __syncthreads();
    }

    // epilogue: per-warp fp32 smem scratch (overlays dead tile data), fused bias
    float* epib = reinterpret_cast<float*>(sm) + warp * 288;  // 16x18 floats
    const int er = lane >> 1;           // row 0..15
    const int ec = (lane & 1) * 8;      // col half
    #pragma unroll
    for (int i = 0; i < 4; i++)
        #pragma unroll
        for (int j = 0; j < 2; j++) {
            wmma::store_matrix_sync(epib, acc[i][j], 18, wmma::mem_row_major);
            __syncwarp();
            const int row = bm + wm * 64 + i * 16 + er;
            const int col = bn + wn * 32 + j * 16 + ec;
            float4 b0 = *reinterpret_cast<const float4*>(&bias[col]);
            float4 b1 = *reinterpret_cast<const float4*>(&bias[col + 4]);
            const float* ep = &epib[er * 18 + ec];
            float4 o0 = {ep[0] + b0.x, ep[1] + b0.y, ep[2] + b0.z, ep[3] + b0.w};
            float4 o1 = {ep[4] + b1.x, ep[5] + b1.y, ep[6] + b1.z, ep[7] + b1.w};
            *reinterpret_cast<float4*>(&C[(size_t)row * GN + col])     = o0;
            *reinterpret_cast<float4*>(&C[(size_t)row * GN + col + 4]) = o1;
            __syncwarp();
        }
}

// Fused Q/K/V projections: blockIdx.z selects the triple. 384 blocks.
__global__ __launch_bounds__(256) void gemm_qkv(
    const float* __restrict__ xq, const float* __restrict__ xk,
    const float* __restrict__ xv,
    const float* __restrict__ Wq, const float* __restrict__ Wk,
    const float* __restrict__ Wv,
    const float* __restrict__ bq, const float* __restrict__ bk,
    const float* __restrict__ bv,
    float* __restrict__ oq, float* __restrict__ ok, float* __restrict__ ov)
{
    __shared__ GemmSmem sm[2];
    const float *A, *W, *bias;
    float* C;
    if (blockIdx.z == 0)      { A = xq; W = Wq; bias = bq; C = oq; }
    else if (blockIdx.z == 1) { A = xk; W = Wk; bias = bk; C = ok; }
    else                      { A = xv; W = Wv; bias = bv; C = ov; }
    gemm_tile(sm, A, W, bias, C);
}

__global__ __launch_bounds__(256) void gemm_one(
    const float* __restrict__ A, const float* __restrict__ W,
    const float* __restrict__ bias, float* __restrict__ C)
{
    __shared__ GemmSmem sm[2];
    gemm_tile(sm, A, W, bias, C);
}

// ---------------------------------------------------------------------------
// Geometric weights: block per (q, b), 256 threads = keys.
// Stores clamped relu weight directly (log folded into softmax algebra).
// ---------------------------------------------------------------------------
__global__ __launch_bounds__(256) void geo_bias(
    const float* __restrict__ box, const float* __restrict__ WGw,
    const float* __restrict__ WGb)
{
    __shared__ float sW[HH * 64];
    __shared__ float sB[HH];
    const int b = blockIdx.y;
    const int q = blockIdx.x;
    const int m = threadIdx.x;

    sW[m] = WGw[m];
    sW[m + 256] = WGw[m + 256];
    if (m < HH) sB[m] = WGb[m];
    __syncthreads();

    const float* bq = box + ((size_t)b * NN + q) * 4;
    const float x0q = bq[0], y0q = bq[1], x1q = bq[2], y1q = bq[3];
    const float cxq = (x0q + x1q) * 0.5f, cyq = (y0q + y1q) * 0.5f;
    const float wq = x1q - x0q + 1.0f,   hq = y1q - y0q + 1.0f;

    const float* bmp = box + ((size_t)b * NN + m) * 4;
    const float x0m = bmp[0], y0m = bmp[1], x1m = bmp[2], y1m = bmp[3];
    const float cxm = (x0m + x1m) * 0.5f, cym = (y0m + y1m) * 0.5f;
    const float wm = x1m - x0m + 1.0f,    hm = y1m - y0m + 1.0f;

    float delta[4];
    delta[0] = logf(fmaxf(fabsf((cxq - cxm) / wq), 0.001f));
    delta[1] = logf(fmaxf(fabsf((cyq - cym) / hq), 0.001f));
    delta[2] = logf(wq / wm);
    delta[3] = logf(hq / hm);

    float acc[HH];
    #pragma unroll
    for (int h = 0; h < HH; h++) acc[h] = sB[h];

    #pragma unroll
    for (int p = 0; p < 4; p++) {
        #pragma unroll
        for (int f = 0; f < 8; f++) {
            float ang = 100.0f * delta[p] * c_dim[f];
            float r = ang - 6.28318530717958647692f *
                            rintf(ang * 0.15915494309189533577f);
            float s, c;
            sincosf(r, &s, &c);
            const int idx = p * 8 + f;
            #pragma unroll
            for (int h = 0; h < HH; h++)
                acc[h] += s * sW[h * 64 + idx] + c * sW[h * 64 + 32 + idx];
        }
    }

    #pragma unroll
    for (int h = 0; h < HH; h++) {
        g_bias[(((size_t)b * HH + h) * NN + q) * NN + m] =
            fmaxf(acc[h], 1e-6f);
    }
}

// ---------------------------------------------------------------------------
// Flash-style attention: block per (qtile=64, h, b), 256 threads.
// ---------------------------------------------------------------------------
__global__ __launch_bounds__(256) void attn2(const int* __restrict__ mask)
{
    const int qt = blockIdx.x, h = blockIdx.y, b = blockIdx.z;
    const int qb = qt * 64;
    const int tid = threadIdx.x;

    __shared__ float sQT[64][64];
    __shared__ float sKT[64][32];
    __shared__ float sV [32][64];
    __shared__ float sP [64][32];
    __shared__ float sM[64], sL[64], sScale[64];

    {
        const int q  = tid >> 2;
        const int d0 = (tid & 3) * 16;
        const float* qp = g_q + ((size_t)(b * NN + qb + q)) * DM + h * DK + d0;
        #pragma unroll
        for (int g = 0; g < 4; g++) {
            float4 f = *reinterpret_cast<const float4*>(qp + g * 4);
            sQT[d0 + g*4 + 0][q] = f.x * 0.125f;
            sQT[d0 + g*4 + 1][q] = f.y * 0.125f;
            sQT[d0 + g*4 + 2][q] = f.z * 0.125f;
            sQT[d0 + g*4 + 3][q] = f.w * 0.125f;
        }
    }
    if (tid < 64) { sM[tid] = -3.0e38f; sL[tid] = 0.0f; }

    const int tq = tid >> 4;
    const int tk = tid & 15;
    const int q0 = tq * 4;
    const int k0 = tk * 2;
    const int d0 = tk * 4;
    const int* mk = mask + b * NN;
    const float* wgb = g_bias + ((size_t)(b * HH + h) * NN) * NN;

    float acc[4][4];
    #pragma unroll
    for (int i = 0; i < 4; i++)
        #pragma unroll
        for (int j = 0; j < 4; j++) acc[i][j] = 0.f;

    for (int kt = 0; kt < 8; kt++) {
        const int kg0 = kt * 32;
        __syncthreads();
        {
            const int k  = tid >> 3;
            const int dd = (tid & 7) * 8;
            const float* kp = g_k + ((size_t)(b * NN + kg0 + k)) * DM + h * DK + dd;
            float4 f0 = *reinterpret_cast<const float4*>(kp);
            float4 f1 = *reinterpret_cast<const float4*>(kp + 4);
            sKT[dd + 0][k] = f0.x; sKT[dd + 1][k] = f0.y;
            sKT[dd + 2][k] = f0.z; sKT[dd + 3][k] = f0.w;
            sKT[dd + 4][k] = f1.x; sKT[dd + 5][k] = f1.y;
            sKT[dd + 6][k] = f1.z; sKT[dd + 7][k] = f1.w;
            const float* vp = g_v + ((size_t)(b * NN + kg0 + k)) * DM + h * DK + dd;
            *reinterpret_cast<float4*>(&sV[k][dd])     =
                *reinterpret_cast<const float4*>(vp);
            *reinterpret_cast<float4*>(&sV[k][dd + 4]) =
                *reinterpret_cast<const float4*>(vp + 4);
        }
        __syncthreads();

        float s00=0,s01=0,s10=0,s11=0,s20=0,s21=0,s30=0,s31=0;
        #pragma unroll 8
        for (int d = 0; d < 64; d++) {
            float4 qa = *reinterpret_cast<const float4*>(&sQT[d][q0]);
            float2 kb = *reinterpret_cast<const float2*>(&sKT[d][k0]);
            s00 += qa.x * kb.x; s01 += qa.x * kb.y;
            s10 += qa.y * kb.x; s11 += qa.y * kb.y;
            s20 += qa.z * kb.x; s21 += qa.z * kb.y;
            s30 += qa.w * kb.x; s31 += qa.w * kb.y;
        }
        float s[4][2] = {{s00,s01},{s10,s11},{s20,s21},{s30,s31}};

        const int km0 = kg0 + k0, km1 = km0 + 1;
        const bool m0 = (mk[km0] == 0), m1 = (mk[km1] == 0);
        float mt[4];
        #pragma unroll
        for (int qi = 0; qi < 4; qi++) {
            if (m0) s[qi][0] = -1e9f;
            if (m1) s[qi][1] = -1e9f;
            mt[qi] = fmaxf(s[qi][0], s[qi][1]);
            #pragma unroll
            for (int o = 1; o < 16; o <<= 1)
                mt[qi] = fmaxf(mt[qi], __shfl_xor_sync(0xffffffffu, mt[qi], o));
        }
        if (tk == 0) {
            #pragma unroll
            for (int qi = 0; qi < 4; qi++) {
                const int q = q0 + qi;
                float m_old = sM[q];
                float m_new = fmaxf(m_old, mt[qi]);
                sM[q] = m_new;
                float scv = __expf(m_old - m_new);
                sScale[q] = scv;
                sL[q] *= scv;
            }
        }
        __syncthreads();

        float sums[4];
        #pragma unroll
        for (int qi = 0; qi < 4; qi++) {
            const int q = q0 + qi;
            const float mq = sM[q];
            float2 wg = *reinterpret_cast<const float2*>(
                &wgb[(size_t)(qb + q) * NN + km0]);
            float p0 = wg.x * __expf(s[qi][0] - mq);
            float p1 = wg.y * __expf(s[qi][1] - mq);
            sP[q][k0]     = p0;
            sP[q][k0 + 1] = p1;
            float su = p0 + p1;
            #pragma unroll
            for (int o = 1; o < 16; o <<= 1)
                su += __shfl_xor_sync(0xffffffffu, su, o);
            sums[qi] = su;
        }
        if (tk == 0) {
            #pragma unroll
            for (int qi = 0; qi < 4; qi++) sL[q0 + qi] += sums[qi];
        }
        __syncthreads();

        float sc4[4];
        #pragma unroll
        for (int qi = 0; qi < 4; qi++) sc4[qi] = sScale[q0 + qi];
        #pragma unroll
        for (int qi = 0; qi < 4; qi++)
            #pragma unroll
            for (int dj = 0; dj < 4; dj++) acc[qi][dj] *= sc4[qi];
        #pragma unroll 4
        for (int k = 0; k < 32; k++) {
            float4 v4 = *reinterpret_cast<const float4*>(&sV[k][d0]);
            float p0 = sP[q0 + 0][k];
            float p1 = sP[q0 + 1][k];
            float p2 = sP[q0 + 2][k];
            float p3 = sP[q0 + 3][k];
            acc[0][0] += p0 * v4.x; acc[0][1] += p0 * v4.y;
            acc[0][2] += p0 * v4.z; acc[0][3] += p0 * v4.w;
            acc[1][0] += p1 * v4.x; acc[1][1] += p1 * v4.y;
            acc[1][2] += p1 * v4.z; acc[1][3] += p1 * v4.w;
            acc[2][0] += p2 * v4.x; acc[2][1] += p2 * v4.y;
            acc[2][2] += p2 * v4.z; acc[2][3] += p2 * v4.w;
            acc[3][0] += p3 * v4.x; acc[3][1] += p3 * v4.y;
            acc[3][2] += p3 * v4.z; acc[3][3] += p3 * v4.w;
        }
    }

    #pragma unroll
    for (int qi = 0; qi < 4; qi++) {
        const int q = q0 + qi;
        const float inv = 1.0f / sL[q];
        float4 o;
        o.x = acc[qi][0] * inv; o.y = acc[qi][1] * inv;
        o.z = acc[qi][2] * inv; o.w = acc[qi][3] * inv;
        *reinterpret_cast<float4*>(
            &g_att[((size_t)(b * NN + qb + q)) * DM + h * DK + d0]) = o;
    }
}

// ---------------------------------------------------------------------------
extern "C" void kernel_launch(void* const* d_in, const int* in_sizes, int n_in,
                              void* d_out, int out_size)
{
    const float* xq  = (const float*)d_in[0];
    const float* xk  = (const float*)d_in[1];
    const float* xv  = (const float*)d_in[2];
    const float* box = (const float*)d_in[3];
    const int*   msk = (const int*)  d_in[4];
    const float* Wq  = (const float*)d_in[5];
    const float* bq  = (const float*)d_in[6];
    const float* Wk  = (const float*)d_in[7];
    const float* bk  = (const float*)d_in[8];
    const float* Wv  = (const float*)d_in[9];
    const float* bv  = (const float*)d_in[10];
    const float* Wo  = (const float*)d_in[11];
    const float* bo  = (const float*)d_in[12];
    const float* WGw = (const float*)d_in[13];
    const float* WGb = (const float*)d_in[14];

    float* out = (float*)d_out;

    void *pq, *pk, *pv, *pa;
    cudaGetSymbolAddress(&pq, g_q);
    cudaGetSymbolAddress(&pk, g_k);
    cudaGetSymbolAddress(&pv, g_v);
    cudaGetSymbolAddress(&pa, g_att);

    // side stream + events for geo ‖ QKV overlap (host-side resources only;
    // capture-safe fork/join pattern)
    static cudaStream_t s_geo = nullptr;
    static cudaEvent_t  e_fork = nullptr, e_join = nullptr;
    if (s_geo == nullptr) {
        cudaStreamCreateWithFlags(&s_geo, cudaStreamNonBlocking);
        cudaEventCreateWithFlags(&e_fork, cudaEventDisableTiming);
        cudaEventCreateWithFlags(&e_join, cudaEventDisableTiming);
    }

    dim3 qkvgrid(GN / 128, GM / 128, 3);    // (4, 32, 3) = 384 blocks
    dim3 ogrid  (GN / 128, GM / 128);       // (4, 32)    = 128 blocks

    // fork: geo_bias runs concurrently with the QKV projections
    cudaEventRecord(e_fork, 0);
    cudaStreamWaitEvent(s_geo, e_fork, 0);
    geo_bias<<<dim3(NN, BB), 256, 0, s_geo>>>(box, WGw, WGb);
    cudaEventRecord(e_join, s_geo);

    gemm_qkv<<<qkvgrid, 256>>>(xq, xk, xv, Wq, Wk, Wv, bq, bk, bv,
                               (float*)pq, (float*)pk, (float*)pv);

    // join: attention needs both QKV and geo weights
    cudaStreamWaitEvent(0, e_join, 0);

    attn2<<<dim3(NN / 64, HH, BB), 256>>>(msk);

    gemm_one<<<ogrid, 256>>>((const float*)pa, Wo, bo, out);
}

// round 11
// speedup vs baseline: 1.1465x; 1.0809x over previous
#include <cuda_runtime.h>
#include <cuda_bf16.h>
#include <mma.h>

using namespace nvcuda;

#define BB 16
#define NN 256
#define DM 512
#define HH 8
#define DK 64

// Scratch (allocation-free rule: __device__ globals)
__device__ float g_q[BB*NN*DM];
__device__ float g_k[BB*NN*DM];
__device__ float g_v[BB*NN*DM];
__device__ float g_bias[BB*HH*NN*NN];   // clamped relu(w_g)
__device__ float g_att[BB*NN*DM];       // attention output pre-Wo

__constant__ float c_dim[8] = {
    1.0f, 0.421696503f, 0.177827941f, 0.0749894209f,
    0.0316227766f, 0.0133352143f, 0.00562341325f, 0.00237137371f};

// ---------------------------------------------------------------------------
// BF16 tensor-core GEMM, 3-term precision split, double-buffered smem,
// VECTORIZED staging (bf16x2 CVT + 16B STS):
//   C = Ahi*Bhi + Ahi*Blo + Alo*Bhi
// Block tile 128x128, BK=16, 256 threads (8 warps 2x4), warp tile 64x32.
// ---------------------------------------------------------------------------
struct GemmSmem {
    __nv_bfloat16 Ah[128][24];   // [m][k], row stride 48B (16B-multiple)
    __nv_bfloat16 Al[128][24];
    __nv_bfloat16 Bh[16][136];   // [k][n], row stride 272B (16B-multiple)
    __nv_bfloat16 Bl[16][136];
};

#define GM 4096
#define GN 512
#define GK 512
#define NKT (GK / 16)   // 32

// convert 8 floats -> hi/lo bf16x2 quads and store as one 16B STS each
__device__ __forceinline__ void cvt_store8(
    __nv_bfloat16* dst_hi, __nv_bfloat16* dst_lo, const float* v)
{
    __nv_bfloat162 h[4], l[4];
    #pragma unroll
    for (int i = 0; i < 4; i++) {
        float2 f = make_float2(v[2*i], v[2*i + 1]);
        h[i] = __float22bfloat162_rn(f);
        float2 hf = __bfloat1622float2(h[i]);
        l[i] = __float22bfloat162_rn(make_float2(f.x - hf.x, f.y - hf.y));
    }
    *reinterpret_cast<uint4*>(dst_hi) = *reinterpret_cast<const uint4*>(h);
    *reinterpret_cast<uint4*>(dst_lo) = *reinterpret_cast<const uint4*>(l);
}

__device__ __forceinline__ void stage_to(
    GemmSmem& sm, const float* va, const float* vb, int ar, int ac, int br, int bc)
{
    cvt_store8(&sm.Ah[ar][ac], &sm.Al[ar][ac], va);
    cvt_store8(&sm.Bh[br][bc], &sm.Bl[br][bc], vb);
}

__device__ __forceinline__ void gemm_tile(
    GemmSmem* sm,   // [2]
    const float* __restrict__ A, const float* __restrict__ W,
    const float* __restrict__ bias, float* __restrict__ C)
{
    const int tid  = threadIdx.x;
    const int warp = tid >> 5;
    const int lane = tid & 31;
    const int wm   = warp >> 2;     // 0..1
    const int wn   = warp & 3;      // 0..3
    const int bm   = blockIdx.y * 128;
    const int bn   = blockIdx.x * 128;

    const int ar = tid >> 1;              // A row 0..127
    const int ac = (tid & 1) * 8;         // A col group
    const int br = tid >> 4;              // B row 0..15
    const int bc = (tid & 15) * 8;        // B col group

    wmma::fragment<wmma::accumulator, 16, 16, 16, float> acc[4][2];
    #pragma unroll
    for (int i = 0; i < 4; i++)
        #pragma unroll
        for (int j = 0; j < 2; j++)
            wmma::fill_fragment(acc[i][j], 0.0f);

    float va[8], vb[8];
    // prologue: ldg k-slab 0 and stage into buffer 0
    {
        const float* ap = &A[(size_t)(bm + ar) * GK + ac];
        float4 f0 = *reinterpret_cast<const float4*>(ap);
        float4 f1 = *reinterpret_cast<const float4*>(ap + 4);
        va[0]=f0.x; va[1]=f0.y; va[2]=f0.z; va[3]=f0.w;
        va[4]=f1.x; va[5]=f1.y; va[6]=f1.z; va[7]=f1.w;
        const float* bp = &W[(size_t)br * GN + bn + bc];
        float4 g0 = *reinterpret_cast<const float4*>(bp);
        float4 g1 = *reinterpret_cast<const float4*>(bp + 4);
        vb[0]=g0.x; vb[1]=g0.y; vb[2]=g0.z; vb[3]=g0.w;
        vb[4]=g1.x; vb[5]=g1.y; vb[6]=g1.z; vb[7]=g1.w;
        stage_to(sm[0], va, vb, ar, ac, br, bc);
    }
    __syncthreads();

    for (int kt = 0; kt < NKT; kt++) {
        const int cur = kt & 1;
        const bool more = (kt + 1 < NKT);

        // ldg next k-slab (latency hidden by mma below)
        if (more) {
            const int k0 = (kt + 1) * 16;
            const float* ap = &A[(size_t)(bm + ar) * GK + k0 + ac];
            float4 f0 = *reinterpret_cast<const float4*>(ap);
            float4 f1 = *reinterpret_cast<const float4*>(ap + 4);
            va[0]=f0.x; va[1]=f0.y; va[2]=f0.z; va[3]=f0.w;
            va[4]=f1.x; va[5]=f1.y; va[6]=f1.z; va[7]=f1.w;
            const float* bp = &W[(size_t)(k0 + br) * GN + bn + bc];
            float4 g0 = *reinterpret_cast<const float4*>(bp);
            float4 g1 = *reinterpret_cast<const float4*>(bp + 4);
            vb[0]=g0.x; vb[1]=g0.y; vb[2]=g0.z; vb[3]=g0.w;
            vb[4]=g1.x; vb[5]=g1.y; vb[6]=g1.z; vb[7]=g1.w;
        }

        // mma on current buffer
        {
            GemmSmem& s = sm[cur];
            wmma::fragment<wmma::matrix_a, 16, 16, 16, __nv_bfloat16,
                           wmma::row_major> ah[4], al[4];
            wmma::fragment<wmma::matrix_b, 16, 16, 16, __nv_bfloat16,
                           wmma::row_major> bh[2], bl[2];
            #pragma unroll
            for (int i = 0; i < 4; i++) {
                wmma::load_matrix_sync(ah[i], &s.Ah[wm * 64 + i * 16][0], 24);
                wmma::load_matrix_sync(al[i], &s.Al[wm * 64 + i * 16][0], 24);
            }
            #pragma unroll
            for (int j = 0; j < 2; j++) {
                wmma::load_matrix_sync(bh[j], &s.Bh[0][wn * 32 + j * 16], 136);
                wmma::load_matrix_sync(bl[j], &s.Bl[0][wn * 32 + j * 16], 136);
            }
            #pragma unroll
            for (int i = 0; i < 4; i++)
                #pragma unroll
                for (int j = 0; j < 2; j++) {
                    wmma::mma_sync(acc[i][j], ah[i], bh[j], acc[i][j]);
                    wmma::mma_sync(acc[i][j], ah[i], bl[j], acc[i][j]);
                    wmma::mma_sync(acc[i][j], al[i], bh[j], acc[i][j]);
                }
        }

        // stage next slab into the other buffer (overlaps with mma in flight)
        if (more)
            stage_to(sm[cur ^ 1], va, vb, ar, ac, br, bc);
        __syncthreads();
    }

    // epilogue: per-warp fp32 smem scratch (overlays dead tile data), fused bias
    float* epib = reinterpret_cast<float*>(sm) + warp * 288;  // 16x18 floats
    const int er = lane >> 1;           // row 0..15
    const int ec = (lane & 1) * 8;      // col half
    #pragma unroll
    for (int i = 0; i < 4; i++)
        #pragma unroll
        for (int j = 0; j < 2; j++) {
            wmma::store_matrix_sync(epib, acc[i][j], 18, wmma::mem_row_major);
            __syncwarp();
            const int row = bm + wm * 64 + i * 16 + er;
            const int col = bn + wn * 32 + j * 16 + ec;
            float4 b0 = *reinterpret_cast<const float4*>(&bias[col]);
            float4 b1 = *reinterpret_cast<const float4*>(&bias[col + 4]);
            const float* ep = &epib[er * 18 + ec];
            float4 o0 = {ep[0] + b0.x, ep[1] + b0.y, ep[2] + b0.z, ep[3] + b0.w};
            float4 o1 = {ep[4] + b1.x, ep[5] + b1.y, ep[6] + b1.z, ep[7] + b1.w};
            *reinterpret_cast<float4*>(&C[(size_t)row * GN + col])     = o0;
            *reinterpret_cast<float4*>(&C[(size_t)row * GN + col + 4]) = o1;
            __syncwarp();
        }
}

// Fused Q/K/V projections: blockIdx.z selects the triple. 384 blocks.
__global__ __launch_bounds__(256) void gemm_qkv(
    const float* __restrict__ xq, const float* __restrict__ xk,
    const float* __restrict__ xv,
    const float* __restrict__ Wq, const float* __restrict__ Wk,
    const float* __restrict__ Wv,
    const float* __restrict__ bq, const float* __restrict__ bk,
    const float* __restrict__ bv,
    float* __restrict__ oq, float* __restrict__ ok, float* __restrict__ ov)
{
    __shared__ GemmSmem sm[2];
    const float *A, *W, *bias;
    float* C;
    if (blockIdx.z == 0)      { A = xq; W = Wq; bias = bq; C = oq; }
    else if (blockIdx.z == 1) { A = xk; W = Wk; bias = bk; C = ok; }
    else                      { A = xv; W = Wv; bias = bv; C = ov; }
    gemm_tile(sm, A, W, bias, C);
}

__global__ __launch_bounds__(256) void gemm_one(
    const float* __restrict__ A, const float* __restrict__ W,
    const float* __restrict__ bias, float* __restrict__ C)
{
    __shared__ GemmSmem sm[2];
    gemm_tile(sm, A, W, bias, C);
}

// ---------------------------------------------------------------------------
// Geometric weights: block per (q, b), 256 threads = keys.
// Stores clamped relu weight directly (log folded into softmax algebra).
// ---------------------------------------------------------------------------
__global__ __launch_bounds__(256) void geo_bias(
    const float* __restrict__ box, const float* __restrict__ WGw,
    const float* __restrict__ WGb)
{
    __shared__ float sW[HH * 64];
    __shared__ float sB[HH];
    const int b = blockIdx.y;
    const int q = blockIdx.x;
    const int m = threadIdx.x;

    sW[m] = WGw[m];
    sW[m + 256] = WGw[m + 256];
    if (m < HH) sB[m] = WGb[m];
    __syncthreads();

    const float* bq = box + ((size_t)b * NN + q) * 4;
    const float x0q = bq[0], y0q = bq[1], x1q = bq[2], y1q = bq[3];
    const float cxq = (x0q + x1q) * 0.5f, cyq = (y0q + y1q) * 0.5f;
    const float wq = x1q - x0q + 1.0f,   hq = y1q - y0q + 1.0f;

    const float* bmp = box + ((size_t)b * NN + m) * 4;
    const float x0m = bmp[0], y0m = bmp[1], x1m = bmp[2], y1m = bmp[3];
    const float cxm = (x0m + x1m) * 0.5f, cym = (y0m + y1m) * 0.5f;
    const float wm = x1m - x0m + 1.0f,    hm = y1m - y0m + 1.0f;

    float delta[4];
    delta[0] = logf(fmaxf(fabsf((cxq - cxm) / wq), 0.001f));
    delta[1] = logf(fmaxf(fabsf((cyq - cym) / hq), 0.001f));
    delta[2] = logf(wq / wm);
    delta[3] = logf(hq / hm);

    float acc[HH];
    #pragma unroll
    for (int h = 0; h < HH; h++) acc[h] = sB[h];

    #pragma unroll
    for (int p = 0; p < 4; p++) {
        #pragma unroll
        for (int f = 0; f < 8; f++) {
            float ang = 100.0f * delta[p] * c_dim[f];
            float r = ang - 6.28318530717958647692f *
                            rintf(ang * 0.15915494309189533577f);
            float s, c;
            sincosf(r, &s, &c);
            const int idx = p * 8 + f;
            #pragma unroll
            for (int h = 0; h < HH; h++)
                acc[h] += s * sW[h * 64 + idx] + c * sW[h * 64 + 32 + idx];
        }
    }

    #pragma unroll
    for (int h = 0; h < HH; h++) {
        g_bias[(((size_t)b * HH + h) * NN + q) * NN + m] =
            fmaxf(acc[h], 1e-6f);
    }
}

// ---------------------------------------------------------------------------
// Flash-style attention: block per (qtile=64, h, b), 256 threads.
// ---------------------------------------------------------------------------
__global__ __launch_bounds__(256) void attn2(const int* __restrict__ mask)
{
    const int qt = blockIdx.x, h = blockIdx.y, b = blockIdx.z;
    const int qb = qt * 64;
    const int tid = threadIdx.x;

    __shared__ float sQT[64][64];
    __shared__ float sKT[64][32];
    __shared__ float sV [32][64];
    __shared__ float sP [64][32];
    __shared__ float sM[64], sL[64], sScale[64];

    {
        const int q  = tid >> 2;
        const int d0 = (tid & 3) * 16;
        const float* qp = g_q + ((size_t)(b * NN + qb + q)) * DM + h * DK + d0;
        #pragma unroll
        for (int g = 0; g < 4; g++) {
            float4 f = *reinterpret_cast<const float4*>(qp + g * 4);
            sQT[d0 + g*4 + 0][q] = f.x * 0.125f;
            sQT[d0 + g*4 + 1][q] = f.y * 0.125f;
            sQT[d0 + g*4 + 2][q] = f.z * 0.125f;
            sQT[d0 + g*4 + 3][q] = f.w * 0.125f;
        }
    }
    if (tid < 64) { sM[tid] = -3.0e38f; sL[tid] = 0.0f; }

    const int tq = tid >> 4;
    const int tk = tid & 15;
    const int q0 = tq * 4;
    const int k0 = tk * 2;
    const int d0 = tk * 4;
    const int* mk = mask + b * NN;
    const float* wgb = g_bias + ((size_t)(b * HH + h) * NN) * NN;

    float acc[4][4];
    #pragma unroll
    for (int i = 0; i < 4; i++)
        #pragma unroll
        for (int j = 0; j < 4; j++) acc[i][j] = 0.f;

    for (int kt = 0; kt < 8; kt++) {
        const int kg0 = kt * 32;
        __syncthreads();
        {
            const int k  = tid >> 3;
            const int dd = (tid & 7) * 8;
            const float* kp = g_k + ((size_t)(b * NN + kg0 + k)) * DM + h * DK + dd;
            float4 f0 = *reinterpret_cast<const float4*>(kp);
            float4 f1 = *reinterpret_cast<const float4*>(kp + 4);
            sKT[dd + 0][k] = f0.x; sKT[dd + 1][k] = f0.y;
            sKT[dd + 2][k] = f0.z; sKT[dd + 3][k] = f0.w;
            sKT[dd + 4][k] = f1.x; sKT[dd + 5][k] = f1.y;
            sKT[dd + 6][k] = f1.z; sKT[dd + 7][k] = f1.w;
            const float* vp = g_v + ((size_t)(b * NN + kg0 + k)) * DM + h * DK + dd;
            *reinterpret_cast<float4*>(&sV[k][dd])     =
                *reinterpret_cast<const float4*>(vp);
            *reinterpret_cast<float4*>(&sV[k][dd + 4]) =
                *reinterpret_cast<const float4*>(vp + 4);
        }
        __syncthreads();

        float s00=0,s01=0,s10=0,s11=0,s20=0,s21=0,s30=0,s31=0;
        #pragma unroll 8
        for (int d = 0; d < 64; d++) {
            float4 qa = *reinterpret_cast<const float4*>(&sQT[d][q0]);
            float2 kb = *reinterpret_cast<const float2*>(&sKT[d][k0]);
            s00 += qa.x * kb.x; s01 += qa.x * kb.y;
            s10 += qa.y * kb.x; s11 += qa.y * kb.y;
            s20 += qa.z * kb.x; s21 += qa.z * kb.y;
            s30 += qa.w * kb.x; s31 += qa.w * kb.y;
        }
        float s[4][2] = {{s00,s01},{s10,s11},{s20,s21},{s30,s31}};

        const int km0 = kg0 + k0, km1 = km0 + 1;
        const bool m0 = (mk[km0] == 0), m1 = (mk[km1] == 0);
        float mt[4];
        #pragma unroll
        for (int qi = 0; qi < 4; qi++) {
            if (m0) s[qi][0] = -1e9f;
            if (m1) s[qi][1] = -1e9f;
            mt[qi] = fmaxf(s[qi][0], s[qi][1]);
            #pragma unroll
            for (int o = 1; o < 16; o <<= 1)
                mt[qi] = fmaxf(mt[qi], __shfl_xor_sync(0xffffffffu, mt[qi], o));
        }
        if (tk == 0) {
            #pragma unroll
            for (int qi = 0; qi < 4; qi++) {
                const int q = q0 + qi;
                float m_old = sM[q];
                float m_new = fmaxf(m_old, mt[qi]);
                sM[q] = m_new;
                float scv = __expf(m_old - m_new);
                sScale[q] = scv;
                sL[q] *= scv;
            }
        }
        __syncthreads();

        float sums[4];
        #pragma unroll
        for (int qi = 0; qi < 4; qi++) {
            const int q = q0 + qi;
            const float mq = sM[q];
            float2 wg = *reinterpret_cast<const float2*>(
                &wgb[(size_t)(qb + q) * NN + km0]);
            float p0 = wg.x * __expf(s[qi][0] - mq);
            float p1 = wg.y * __expf(s[qi][1] - mq);
            sP[q][k0]     = p0;
            sP[q][k0 + 1] = p1;
            float su = p0 + p1;
            #pragma unroll
            for (int o = 1; o < 16; o <<= 1)
                su += __shfl_xor_sync(0xffffffffu, su, o);
            sums[qi] = su;
        }
        if (tk == 0) {
            #pragma unroll
            for (int qi = 0; qi < 4; qi++) sL[q0 + qi] += sums[qi];
        }
        __syncthreads();

        float sc4[4];
        #pragma unroll
        for (int qi = 0; qi < 4; qi++) sc4[qi] = sScale[q0 + qi];
        #pragma unroll
        for (int qi = 0; qi < 4; qi++)
            #pragma unroll
            for (int dj = 0; dj < 4; dj++) acc[qi][dj] *= sc4[qi];
        #pragma unroll 4
        for (int k = 0; k < 32; k++) {
            float4 v4 = *reinterpret_cast<const float4*>(&sV[k][d0]);
            float p0 = sP[q0 + 0][k];
            float p1 = sP[q0 + 1][k];
            float p2 = sP[q0 + 2][k];
            float p3 = sP[q0 + 3][k];
            acc[0][0] += p0 * v4.x; acc[0][1] += p0 * v4.y;
            acc[0][2] += p0 * v4.z; acc[0][3] += p0 * v4.w;
            acc[1][0] += p1 * v4.x; acc[1][1] += p1 * v4.y;
            acc[1][2] += p1 * v4.z; acc[1][3] += p1 * v4.w;
            acc[2][0] += p2 * v4.x; acc[2][1] += p2 * v4.y;
            acc[2][2] += p2 * v4.z; acc[2][3] += p2 * v4.w;
            acc[3][0] += p3 * v4.x; acc[3][1] += p3 * v4.y;
            acc[3][2] += p3 * v4.z; acc[3][3] += p3 * v4.w;
        }
    }

    #pragma unroll
    for (int qi = 0; qi < 4; qi++) {
        const int q = q0 + qi;
        const float inv = 1.0f / sL[q];
        float4 o;
        o.x = acc[qi][0] * inv; o.y = acc[qi][1] * inv;
        o.z = acc[qi][2] * inv; o.w = acc[qi][3] * inv;
        *reinterpret_cast<float4*>(
            &g_att[((size_t)(b * NN + qb + q)) * DM + h * DK + d0]) = o;
    }
}

// ---------------------------------------------------------------------------
extern "C" void kernel_launch(void* const* d_in, const int* in_sizes, int n_in,
                              void* d_out, int out_size)
{
    const float* xq  = (const float*)d_in[0];
    const float* xk  = (const float*)d_in[1];
    const float* xv  = (const float*)d_in[2];
    const float* box = (const float*)d_in[3];
    const int*   msk = (const int*)  d_in[4];
    const float* Wq  = (const float*)d_in[5];
    const float* bq  = (const float*)d_in[6];
    const float* Wk  = (const float*)d_in[7];
    const float* bk  = (const float*)d_in[8];
    const float* Wv  = (const float*)d_in[9];
    const float* bv  = (const float*)d_in[10];
    const float* Wo  = (const float*)d_in[11];
    const float* bo  = (const float*)d_in[12];
    const float* WGw = (const float*)d_in[13];
    const float* WGb = (const float*)d_in[14];

    float* out = (float*)d_out;

    void *pq, *pk, *pv, *pa;
    cudaGetSymbolAddress(&pq, g_q);
    cudaGetSymbolAddress(&pk, g_k);
    cudaGetSymbolAddress(&pv, g_v);
    cudaGetSymbolAddress(&pa, g_att);

    // side stream + events for geo ‖ QKV overlap (host-side resources only;
    // capture-safe fork/join pattern)
    static cudaStream_t s_geo = nullptr;
    static cudaEvent_t  e_fork = nullptr, e_join = nullptr;
    if (s_geo == nullptr) {
        cudaStreamCreateWithFlags(&s_geo, cudaStreamNonBlocking);
        cudaEventCreateWithFlags(&e_fork, cudaEventDisableTiming);
        cudaEventCreateWithFlags(&e_join, cudaEventDisableTiming);
    }

    dim3 qkvgrid(GN / 128, GM / 128, 3);    // (4, 32, 3) = 384 blocks
    dim3 ogrid  (GN / 128, GM / 128);       // (4, 32)    = 128 blocks

    // fork: geo_bias runs concurrently with the QKV projections
    cudaEventRecord(e_fork, 0);
    cudaStreamWaitEvent(s_geo, e_fork, 0);
    geo_bias<<<dim3(NN, BB), 256, 0, s_geo>>>(box, WGw, WGb);
    cudaEventRecord(e_join, s_geo);

    gemm_qkv<<<qkvgrid, 256>>>(xq, xk, xv, Wq, Wk, Wv, bq, bk, bv,
                               (float*)pq, (float*)pk, (float*)pv);

    // join: attention needs both QKV and geo weights
    cudaStreamWaitEvent(0, e_join, 0);

    attn2<<<dim3(NN / 64, HH, BB), 256>>>(msk);

    gemm_one<<<ogrid, 256>>>((const float*)pa, Wo, bo, out);
}

// round 12
// speedup vs baseline: 1.2195x; 1.0637x over previous
#include <cuda_runtime.h>
#include <cuda_bf16.h>
#include <mma.h>

using namespace nvcuda;

#define BB 16
#define NN 256
#define DM 512
#define HH 8
#define DK 64

// Scratch (allocation-free rule: __device__ globals)
__device__ float g_q[BB*NN*DM];
__device__ float g_k[BB*NN*DM];
__device__ float g_v[BB*NN*DM];
__device__ float g_bias[BB*HH*NN*NN];   // clamped relu(w_g)
__device__ float g_att[BB*NN*DM];       // attention output pre-Wo

__constant__ float c_dim[8] = {
    1.0f, 0.421696503f, 0.177827941f, 0.0749894209f,
    0.0316227766f, 0.0133352143f, 0.00562341325f, 0.00237137371f};

#define GM 4096
#define GN 512
#define GK 512
#define NKT (GK / 16)   // 32

// convert 8 floats -> hi/lo bf16x2 quads, one 16B STS each
__device__ __forceinline__ void cvt_store8(
    __nv_bfloat16* dst_hi, __nv_bfloat16* dst_lo, const float* v)
{
    __nv_bfloat162 h[4], l[4];
    #pragma unroll
    for (int i = 0; i < 4; i++) {
        float2 f = make_float2(v[2*i], v[2*i + 1]);
        h[i] = __float22bfloat162_rn(f);
        float2 hf = __bfloat1622float2(h[i]);
        l[i] = __float22bfloat162_rn(make_float2(f.x - hf.x, f.y - hf.y));
    }
    *reinterpret_cast<uint4*>(dst_hi) = *reinterpret_cast<const uint4*>(h);
    *reinterpret_cast<uint4*>(dst_lo) = *reinterpret_cast<const uint4*>(l);
}
__device__ __forceinline__ void cvt_store16(
    __nv_bfloat16* dst_hi, __nv_bfloat16* dst_lo, const float* v)
{
    cvt_store8(dst_hi, dst_lo, v);
    cvt_store8(dst_hi + 8, dst_lo + 8, v + 8);
}

// ---------------------------------------------------------------------------
// QKV GEMM: 128x128 tile (R11 best config — unchanged)
// ---------------------------------------------------------------------------
struct GemmSmem {
    __nv_bfloat16 Ah[128][24];
    __nv_bfloat16 Al[128][24];
    __nv_bfloat16 Bh[16][136];
    __nv_bfloat16 Bl[16][136];
};

__device__ __forceinline__ void stage_to(
    GemmSmem& sm, const float* va, const float* vb, int ar, int ac, int br, int bc)
{
    cvt_store8(&sm.Ah[ar][ac], &sm.Al[ar][ac], va);
    cvt_store8(&sm.Bh[br][bc], &sm.Bl[br][bc], vb);
}

__device__ __forceinline__ void gemm_tile(
    GemmSmem* sm,
    const float* __restrict__ A, const float* __restrict__ W,
    const float* __restrict__ bias, float* __restrict__ C)
{
    const int tid  = threadIdx.x;
    const int warp = tid >> 5;
    const int lane = tid & 31;
    const int wm   = warp >> 2;
    const int wn   = warp & 3;
    const int bm   = blockIdx.y * 128;
    const int bn   = blockIdx.x * 128;

    const int ar = tid >> 1;
    const int ac = (tid & 1) * 8;
    const int br = tid >> 4;
    const int bc = (tid & 15) * 8;

    wmma::fragment<wmma::accumulator, 16, 16, 16, float> acc[4][2];
    #pragma unroll
    for (int i = 0; i < 4; i++)
        #pragma unroll
        for (int j = 0; j < 2; j++)
            wmma::fill_fragment(acc[i][j], 0.0f);

    float va[8], vb[8];
    {
        const float* ap = &A[(size_t)(bm + ar) * GK + ac];
        float4 f0 = *reinterpret_cast<const float4*>(ap);
        float4 f1 = *reinterpret_cast<const float4*>(ap + 4);
        va[0]=f0.x; va[1]=f0.y; va[2]=f0.z; va[3]=f0.w;
        va[4]=f1.x; va[5]=f1.y; va[6]=f1.z; va[7]=f1.w;
        const float* bp = &W[(size_t)br * GN + bn + bc];
        float4 g0 = *reinterpret_cast<const float4*>(bp);
        float4 g1 = *reinterpret_cast<const float4*>(bp + 4);
        vb[0]=g0.x; vb[1]=g0.y; vb[2]=g0.z; vb[3]=g0.w;
        vb[4]=g1.x; vb[5]=g1.y; vb[6]=g1.z; vb[7]=g1.w;
        stage_to(sm[0], va, vb, ar, ac, br, bc);
    }
    __syncthreads();

    for (int kt = 0; kt < NKT; kt++) {
        const int cur = kt & 1;
        const bool more = (kt + 1 < NKT);
        if (more) {
            const int k0 = (kt + 1) * 16;
            const float* ap = &A[(size_t)(bm + ar) * GK + k0 + ac];
            float4 f0 = *reinterpret_cast<const float4*>(ap);
            float4 f1 = *reinterpret_cast<const float4*>(ap + 4);
            va[0]=f0.x; va[1]=f0.y; va[2]=f0.z; va[3]=f0.w;
            va[4]=f1.x; va[5]=f1.y; va[6]=f1.z; va[7]=f1.w;
            const float* bp = &W[(size_t)(k0 + br) * GN + bn + bc];
            float4 g0 = *reinterpret_cast<const float4*>(bp);
            float4 g1 = *reinterpret_cast<const float4*>(bp + 4);
            vb[0]=g0.x; vb[1]=g0.y; vb[2]=g0.z; vb[3]=g0.w;
            vb[4]=g1.x; vb[5]=g1.y; vb[6]=g1.z; vb[7]=g1.w;
        }
        {
            GemmSmem& s = sm[cur];
            wmma::fragment<wmma::matrix_a, 16, 16, 16, __nv_bfloat16,
                           wmma::row_major> ah[4], al[4];
            wmma::fragment<wmma::matrix_b, 16, 16, 16, __nv_bfloat16,
                           wmma::row_major> bh[2], bl[2];
            #pragma unroll
            for (int i = 0; i < 4; i++) {
                wmma::load_matrix_sync(ah[i], &s.Ah[wm * 64 + i * 16][0], 24);
                wmma::load_matrix_sync(al[i], &s.Al[wm * 64 + i * 16][0], 24);
            }
            #pragma unroll
            for (int j = 0; j < 2; j++) {
                wmma::load_matrix_sync(bh[j], &s.Bh[0][wn * 32 + j * 16], 136);
                wmma::load_matrix_sync(bl[j], &s.Bl[0][wn * 32 + j * 16], 136);
            }
            #pragma unroll
            for (int i = 0; i < 4; i++)
                #pragma unroll
                for (int j = 0; j < 2; j++) {
                    wmma::mma_sync(acc[i][j], ah[i], bh[j], acc[i][j]);
                    wmma::mma_sync(acc[i][j], ah[i], bl[j], acc[i][j]);
                    wmma::mma_sync(acc[i][j], al[i], bh[j], acc[i][j]);
                }
        }
        if (more)
            stage_to(sm[cur ^ 1], va, vb, ar, ac, br, bc);
        __syncthreads();
    }

    float* epib = reinterpret_cast<float*>(sm) + warp * 288;
    const int er = lane >> 1;
    const int ec = (lane & 1) * 8;
    #pragma unroll
    for (int i = 0; i < 4; i++)
        #pragma unroll
        for (int j = 0; j < 2; j++) {
            wmma::store_matrix_sync(epib, acc[i][j], 18, wmma::mem_row_major);
            __syncwarp();
            const int row = bm + wm * 64 + i * 16 + er;
            const int col = bn + wn * 32 + j * 16 + ec;
            float4 b0 = *reinterpret_cast<const float4*>(&bias[col]);
            float4 b1 = *reinterpret_cast<const float4*>(&bias[col + 4]);
            const float* ep = &epib[er * 18 + ec];
            float4 o0 = {ep[0] + b0.x, ep[1] + b0.y, ep[2] + b0.z, ep[3] + b0.w};
            float4 o1 = {ep[4] + b1.x, ep[5] + b1.y, ep[6] + b1.z, ep[7] + b1.w};
            *reinterpret_cast<float4*>(&C[(size_t)row * GN + col])     = o0;
            *reinterpret_cast<float4*>(&C[(size_t)row * GN + col + 4]) = o1;
            __syncwarp();
        }
}

__global__ __launch_bounds__(256) void gemm_qkv(
    const float* __restrict__ xq, const float* __restrict__ xk,
    const float* __restrict__ xv,
    const float* __restrict__ Wq, const float* __restrict__ Wk,
    const float* __restrict__ Wv,
    const float* __restrict__ bq, const float* __restrict__ bk,
    const float* __restrict__ bv,
    float* __restrict__ oq, float* __restrict__ ok, float* __restrict__ ov)
{
    __shared__ GemmSmem sm[2];
    const float *A, *W, *bias;
    float* C;
    if (blockIdx.z == 0)      { A = xq; W = Wq; bias = bq; C = oq; }
    else if (blockIdx.z == 1) { A = xk; W = Wk; bias = bk; C = ok; }
    else                      { A = xv; W = Wv; bias = bv; C = ov; }
    gemm_tile(sm, A, W, bias, C);
}

// ---------------------------------------------------------------------------
// Output GEMM: 64x128 tile -> 256 blocks -> 2 CTAs/SM, one wave
// ---------------------------------------------------------------------------
struct GemmSmem64 {
    __nv_bfloat16 Ah[64][24];
    __nv_bfloat16 Al[64][24];
    __nv_bfloat16 Bh[16][136];
    __nv_bfloat16 Bl[16][136];
};

__global__ __launch_bounds__(256) void gemm_one64(
    const float* __restrict__ A, const float* __restrict__ W,
    const float* __restrict__ bias, float* __restrict__ C)
{
    __shared__ GemmSmem64 sm[2];
    const int tid  = threadIdx.x;
    const int warp = tid >> 5;
    const int lane = tid & 31;
    const int wm   = warp >> 2;     // 0..1 -> rows
    const int wn   = warp & 3;      // 0..3 -> cols
    const int bm   = blockIdx.y * 64;
    const int bn   = blockIdx.x * 128;

    const int ar = tid >> 1;              // 0..127 (only tid<128 stages A)
    const int ac = (tid & 1) * 8;
    const int br = tid >> 4;
    const int bc = (tid & 15) * 8;
    const bool doA = (tid < 128);

    wmma::fragment<wmma::accumulator, 16, 16, 16, float> acc[2][2];
    #pragma unroll
    for (int i = 0; i < 2; i++)
        #pragma unroll
        for (int j = 0; j < 2; j++)
            wmma::fill_fragment(acc[i][j], 0.0f);

    float va[8], vb[8];
    {
        if (doA) {
            const float* ap = &A[(size_t)(bm + ar) * GK + ac];
            float4 f0 = *reinterpret_cast<const float4*>(ap);
            float4 f1 = *reinterpret_cast<const float4*>(ap + 4);
            va[0]=f0.x; va[1]=f0.y; va[2]=f0.z; va[3]=f0.w;
            va[4]=f1.x; va[5]=f1.y; va[6]=f1.z; va[7]=f1.w;
        }
        const float* bp = &W[(size_t)br * GN + bn + bc];
        float4 g0 = *reinterpret_cast<const float4*>(bp);
        float4 g1 = *reinterpret_cast<const float4*>(bp + 4);
        vb[0]=g0.x; vb[1]=g0.y; vb[2]=g0.z; vb[3]=g0.w;
        vb[4]=g1.x; vb[5]=g1.y; vb[6]=g1.z; vb[7]=g1.w;
        if (doA) cvt_store8(&sm[0].Ah[ar][ac], &sm[0].Al[ar][ac], va);
        cvt_store8(&sm[0].Bh[br][bc], &sm[0].Bl[br][bc], vb);
    }
    __syncthreads();

    for (int kt = 0; kt < NKT; kt++) {
        const int cur = kt & 1;
        const bool more = (kt + 1 < NKT);
        if (more) {
            const int k0 = (kt + 1) * 16;
            if (doA) {
                const float* ap = &A[(size_t)(bm + ar) * GK + k0 + ac];
                float4 f0 = *reinterpret_cast<const float4*>(ap);
                float4 f1 = *reinterpret_cast<const float4*>(ap + 4);
                va[0]=f0.x; va[1]=f0.y; va[2]=f0.z; va[3]=f0.w;
                va[4]=f1.x; va[5]=f1.y; va[6]=f1.z; va[7]=f1.w;
            }
            const float* bp = &W[(size_t)(k0 + br) * GN + bn + bc];
            float4 g0 = *reinterpret_cast<const float4*>(bp);
            float4 g1 = *reinterpret_cast<const float4*>(bp + 4);
            vb[0]=g0.x; vb[1]=g0.y; vb[2]=g0.z; vb[3]=g0.w;
            vb[4]=g1.x; vb[5]=g1.y; vb[6]=g1.z; vb[7]=g1.w;
        }
        {
            GemmSmem64& s = sm[cur];
            wmma::fragment<wmma::matrix_a, 16, 16, 16, __nv_bfloat16,
                           wmma::row_major> ah[2], al[2];
            wmma::fragment<wmma::matrix_b, 16, 16, 16, __nv_bfloat16,
                           wmma::row_major> bh[2], bl[2];
            #pragma unroll
            for (int i = 0; i < 2; i++) {
                wmma::load_matrix_sync(ah[i], &s.Ah[wm * 32 + i * 16][0], 24);
                wmma::load_matrix_sync(al[i], &s.Al[wm * 32 + i * 16][0], 24);
            }
            #pragma unroll
            for (int j = 0; j < 2; j++) {
                wmma::load_matrix_sync(bh[j], &s.Bh[0][wn * 32 + j * 16], 136);
                wmma::load_matrix_sync(bl[j], &s.Bl[0][wn * 32 + j * 16], 136);
            }
            #pragma unroll
            for (int i = 0; i < 2; i++)
                #pragma unroll
                for (int j = 0; j < 2; j++) {
                    wmma::mma_sync(acc[i][j], ah[i], bh[j], acc[i][j]);
                    wmma::mma_sync(acc[i][j], ah[i], bl[j], acc[i][j]);
                    wmma::mma_sync(acc[i][j], al[i], bh[j], acc[i][j]);
                }
        }
        if (more) {
            if (doA) cvt_store8(&sm[cur ^ 1].Ah[ar][ac], &sm[cur ^ 1].Al[ar][ac], va);
            cvt_store8(&sm[cur ^ 1].Bh[br][bc], &sm[cur ^ 1].Bl[br][bc], vb);
        }
        __syncthreads();
    }

    float* epib = reinterpret_cast<float*>(sm) + warp * 288;
    const int er = lane >> 1;
    const int ec = (lane & 1) * 8;
    #pragma unroll
    for (int i = 0; i < 2; i++)
        #pragma unroll
        for (int j = 0; j < 2; j++) {
            wmma::store_matrix_sync(epib, acc[i][j], 18, wmma::mem_row_major);
            __syncwarp();
            const int row = bm + wm * 32 + i * 16 + er;
            const int col = bn + wn * 32 + j * 16 + ec;
            float4 b0 = *reinterpret_cast<const float4*>(&bias[col]);
            float4 b1 = *reinterpret_cast<const float4*>(&bias[col + 4]);
            const float* ep = &epib[er * 18 + ec];
            float4 o0 = {ep[0] + b0.x, ep[1] + b0.y, ep[2] + b0.z, ep[3] + b0.w};
            float4 o1 = {ep[4] + b1.x, ep[5] + b1.y, ep[6] + b1.z, ep[7] + b1.w};
            *reinterpret_cast<float4*>(&C[(size_t)row * GN + col])     = o0;
            *reinterpret_cast<float4*>(&C[(size_t)row * GN + col + 4]) = o1;
            __syncwarp();
        }
}

// ---------------------------------------------------------------------------
// Geometric weights (unchanged)
// ---------------------------------------------------------------------------
__global__ __launch_bounds__(256) void geo_bias(
    const float* __restrict__ box, const float* __restrict__ WGw,
    const float* __restrict__ WGb)
{
    __shared__ float sW[HH * 64];
    __shared__ float sB[HH];
    const int b = blockIdx.y;
    const int q = blockIdx.x;
    const int m = threadIdx.x;

    sW[m] = WGw[m];
    sW[m + 256] = WGw[m + 256];
    if (m < HH) sB[m] = WGb[m];
    __syncthreads();

    const float* bq = box + ((size_t)b * NN + q) * 4;
    const float x0q = bq[0], y0q = bq[1], x1q = bq[2], y1q = bq[3];
    const float cxq = (x0q + x1q) * 0.5f, cyq = (y0q + y1q) * 0.5f;
    const float wq = x1q - x0q + 1.0f,   hq = y1q - y0q + 1.0f;

    const float* bmp = box + ((size_t)b * NN + m) * 4;
    const float x0m = bmp[0], y0m = bmp[1], x1m = bmp[2], y1m = bmp[3];
    const float cxm = (x0m + x1m) * 0.5f, cym = (y0m + y1m) * 0.5f;
    const float wm = x1m - x0m + 1.0f,    hm = y1m - y0m + 1.0f;

    float delta[4];
    delta[0] = logf(fmaxf(fabsf((cxq - cxm) / wq), 0.001f));
    delta[1] = logf(fmaxf(fabsf((cyq - cym) / hq), 0.001f));
    delta[2] = logf(wq / wm);
    delta[3] = logf(hq / hm);

    float acc[HH];
    #pragma unroll
    for (int h = 0; h < HH; h++) acc[h] = sB[h];

    #pragma unroll
    for (int p = 0; p < 4; p++) {
        #pragma unroll
        for (int f = 0; f < 8; f++) {
            float ang = 100.0f * delta[p] * c_dim[f];
            float r = ang - 6.28318530717958647692f *
                            rintf(ang * 0.15915494309189533577f);
            float s, c;
            sincosf(r, &s, &c);
            const int idx = p * 8 + f;
            #pragma unroll
            for (int h = 0; h < HH; h++)
                acc[h] += s * sW[h * 64 + idx] + c * sW[h * 64 + 32 + idx];
        }
    }

    #pragma unroll
    for (int h = 0; h < HH; h++) {
        g_bias[(((size_t)b * HH + h) * NN + q) * NN + m] =
            fmaxf(acc[h], 1e-6f);
    }
}

// ---------------------------------------------------------------------------
// Tensor-core attention: block per (qtile=64, h, b), 256 threads.
// Scores and PV on bf16 wmma with 2-term splits; online softmax in smem.
// ---------------------------------------------------------------------------
struct AttnSmem {
    __nv_bfloat16 Qh[64][72], Ql[64][72];
    __nv_bfloat16 Kh[64][72], Kl[64][72];
    __nv_bfloat16 Vh[64][72], Vl[64][72];
    __nv_bfloat16 Ph[64][72], Pl[64][72];
    float S [64][68];
    float Os[64][68];
    float Od[64][68];
    float M[64], L[64], Sc[64];
};

__global__ __launch_bounds__(256) void attn3(const int* __restrict__ mask)
{
    extern __shared__ char smraw[];
    AttnSmem& sm = *reinterpret_cast<AttnSmem*>(smraw);

    const int qt = blockIdx.x, h = blockIdx.y, b = blockIdx.z;
    const int qb = qt * 64;
    const int tid  = threadIdx.x;
    const int warp = tid >> 5;
    const int wm   = warp >> 2;   // 0..1
    const int wn   = warp & 3;    // 0..3
    const int rq   = tid >> 2;    // 0..63 (row for SIMT phases)
    const int sub  = tid & 3;
    const int d0   = sub * 16;    // 16-elem column slice

    // load Q tile, pre-scale 1/sqrt(dk), split to bf16 hi/lo
    {
        const float* qp = g_q + ((size_t)(b * NN + qb + rq)) * DM + h * DK + d0;
        float v[16];
        #pragma unroll
        for (int g = 0; g < 4; g++) {
            float4 f = *reinterpret_cast<const float4*>(qp + g * 4);
            v[g*4+0] = f.x * 0.125f; v[g*4+1] = f.y * 0.125f;
            v[g*4+2] = f.z * 0.125f; v[g*4+3] = f.w * 0.125f;
        }
        cvt_store16(&sm.Qh[rq][d0], &sm.Ql[rq][d0], v);
    }
    if (tid < 64) { sm.M[tid] = -3.0e38f; sm.L[tid] = 0.0f; }
    #pragma unroll
    for (int j = 0; j < 16; j++) sm.Os[rq][d0 + j] = 0.0f;

    const int* mk = mask + b * NN;
    const float* wgrow = g_bias + ((size_t)(b * HH + h) * NN + qb) * NN + (size_t)rq * NN;

    for (int kt = 0; kt < 4; kt++) {
        const int kg0 = kt * 64;
        __syncthreads();
        // stage K and V tiles (bf16 hi/lo)
        {
            float v[16];
            const float* kp = g_k + ((size_t)(b * NN + kg0 + rq)) * DM + h * DK + d0;
            #pragma unroll
            for (int g = 0; g < 4; g++) {
                float4 f = *reinterpret_cast<const float4*>(kp + g * 4);
                v[g*4+0]=f.x; v[g*4+1]=f.y; v[g*4+2]=f.z; v[g*4+3]=f.w;
            }
            cvt_store16(&sm.Kh[rq][d0], &sm.Kl[rq][d0], v);
            const float* vp = g_v + ((size_t)(b * NN + kg0 + rq)) * DM + h * DK + d0;
            #pragma unroll
            for (int g = 0; g < 4; g++) {
                float4 f = *reinterpret_cast<const float4*>(vp + g * 4);
                v[g*4+0]=f.x; v[g*4+1]=f.y; v[g*4+2]=f.z; v[g*4+3]=f.w;
            }
            cvt_store16(&sm.Vh[rq][d0], &sm.Vl[rq][d0], v);
        }
        __syncthreads();

        // scores: warp tile 32q x 16k, S = Q·K^T (2-term split)
        {
            wmma::fragment<wmma::accumulator, 16, 16, 16, float> sa[2];
            #pragma unroll
            for (int i = 0; i < 2; i++) wmma::fill_fragment(sa[i], 0.0f);
            #pragma unroll
            for (int kk = 0; kk < 4; kk++) {
                wmma::fragment<wmma::matrix_b, 16, 16, 16, __nv_bfloat16,
                               wmma::col_major> bh, bl;
                wmma::load_matrix_sync(bh, &sm.Kh[wn * 16][kk * 16], 72);
                wmma::load_matrix_sync(bl, &sm.Kl[wn * 16][kk * 16], 72);
                #pragma unroll
                for (int i = 0; i < 2; i++) {
                    wmma::fragment<wmma::matrix_a, 16, 16, 16, __nv_bfloat16,
                                   wmma::row_major> ah, al;
                    wmma::load_matrix_sync(ah, &sm.Qh[wm * 32 + i * 16][kk * 16], 72);
                    wmma::load_matrix_sync(al, &sm.Ql[wm * 32 + i * 16][kk * 16], 72);
                    wmma::mma_sync(sa[i], ah, bh, sa[i]);
                    wmma::mma_sync(sa[i], ah, bl, sa[i]);
                    wmma::mma_sync(sa[i], al, bh, sa[i]);
                }
            }
            #pragma unroll
            for (int i = 0; i < 2; i++)
                wmma::store_matrix_sync(&sm.S[wm * 32 + i * 16][wn * 16], sa[i],
                                        68, wmma::mem_row_major);
        }
        __syncthreads();

        // online softmax bookkeeping (thread = q-row rq, keys d0..d0+15)
        float s[16];
        {
            const int4* mi = reinterpret_cast<const int4*>(&mk[kg0 + d0]);
            int mv[16];
            #pragma unroll
            for (int g = 0; g < 4; g++) {
                int4 m4 = mi[g];
                mv[g*4+0]=m4.x; mv[g*4+1]=m4.y; mv[g*4+2]=m4.z; mv[g*4+3]=m4.w;
            }
            float mt = -3.0e38f;
            #pragma unroll
            for (int j = 0; j < 16; j++) {
                float sv = sm.S[rq][d0 + j];
                if (mv[j] == 0) sv = -1e9f;
                s[j] = sv;
                mt = fmaxf(mt, sv);
            }
            mt = fmaxf(mt, __shfl_xor_sync(0xffffffffu, mt, 1));
            mt = fmaxf(mt, __shfl_xor_sync(0xffffffffu, mt, 2));
            if (sub == 0) {
                float m_old = sm.M[rq];
                float m_new = fmaxf(m_old, mt);
                sm.M[rq] = m_new;
                float sc = __expf(m_old - m_new);
                sm.Sc[rq] = sc;
                sm.L[rq] *= sc;
            }
            __syncwarp();
            const float mq = sm.M[rq];
            float p[16];
            float psum = 0.0f;
            const float* wgp = wgrow + kg0 + d0;
            #pragma unroll
            for (int g = 0; g < 4; g++) {
                float4 w4 = *reinterpret_cast<const float4*>(wgp + g * 4);
                float wv[4] = {w4.x, w4.y, w4.z, w4.w};
                #pragma unroll
                for (int u = 0; u < 4; u++) {
                    float pv = wv[u] * __expf(s[g*4+u] - mq);
                    p[g*4+u] = pv;
                    psum += pv;
                }
            }
            cvt_store16(&sm.Ph[rq][d0], &sm.Pl[rq][d0], p);
            psum += __shfl_xor_sync(0xffffffffu, psum, 1);
            psum += __shfl_xor_sync(0xffffffffu, psum, 2);
            if (sub == 0) sm.L[rq] += psum;
        }
        __syncthreads();

        // PV: warp tile 32q x 16d, Od = P·V (2-term split)
        {
            wmma::fragment<wmma::accumulator, 16, 16, 16, float> pa[2];
            #pragma unroll
            for (int i = 0; i < 2; i++) wmma::fill_fragment(pa[i], 0.0f);
            #pragma unroll
            for (int kk = 0; kk < 4; kk++) {
                wmma::fragment<wmma::matrix_b, 16, 16, 16, __nv_bfloat16,
                               wmma::row_major> bh, bl;
                wmma::load_matrix_sync(bh, &sm.Vh[kk * 16][wn * 16], 72);
                wmma::load_matrix_sync(bl, &sm.Vl[kk * 16][wn * 16], 72);
                #pragma unroll
                for (int i = 0; i < 2; i++) {
                    wmma::fragment<wmma::matrix_a, 16, 16, 16, __nv_bfloat16,
                                   wmma::row_major> ah, al;
                    wmma::load_matrix_sync(ah, &sm.Ph[wm * 32 + i * 16][kk * 16], 72);
                    wmma::load_matrix_sync(al, &sm.Pl[wm * 32 + i * 16][kk * 16], 72);
                    wmma::mma_sync(pa[i], ah, bh, pa[i]);
                    wmma::mma_sync(pa[i], ah, bl, pa[i]);
                    wmma::mma_sync(pa[i], al, bh, pa[i]);
                }
            }
            #pragma unroll
            for (int i = 0; i < 2; i++)
                wmma::store_matrix_sync(&sm.Od[wm * 32 + i * 16][wn * 16], pa[i],
                                        68, wmma::mem_row_major);
        }
        __syncthreads();

        // merge: Os = Os*scale + Od
        {
            const float sc = sm.Sc[rq];
            #pragma unroll
            for (int j = 0; j < 16; j++)
                sm.Os[rq][d0 + j] = sm.Os[rq][d0 + j] * sc + sm.Od[rq][d0 + j];
        }
    }
    __syncthreads();

    // epilogue: normalize and store
    {
        const float inv = 1.0f / sm.L[rq];
        float* op = g_att + ((size_t)(b * NN + qb + rq)) * DM + h * DK + d0;
        #pragma unroll
        for (int g = 0; g < 4; g++) {
            float4 o;
            o.x = sm.Os[rq][d0 + g*4 + 0] * inv;
            o.y = sm.Os[rq][d0 + g*4 + 1] * inv;
            o.z = sm.Os[rq][d0 + g*4 + 2] * inv;
            o.w = sm.Os[rq][d0 + g*4 + 3] * inv;
            *reinterpret_cast<float4*>(op + g * 4) = o;
        }
    }
}

// ---------------------------------------------------------------------------
extern "C" void kernel_launch(void* const* d_in, const int* in_sizes, int n_in,
                              void* d_out, int out_size)
{
    const float* xq  = (const float*)d_in[0];
    const float* xk  = (const float*)d_in[1];
    const float* xv  = (const float*)d_in[2];
    const float* box = (const float*)d_in[3];
    const int*   msk = (const int*)  d_in[4];
    const float* Wq  = (const float*)d_in[5];
    const float* bq  = (const float*)d_in[6];
    const float* Wk  = (const float*)d_in[7];
    const float* bk  = (const float*)d_in[8];
    const float* Wv  = (const float*)d_in[9];
    const float* bv  = (const float*)d_in[10];
    const float* Wo  = (const float*)d_in[11];
    const float* bo  = (const float*)d_in[12];
    const float* WGw = (const float*)d_in[13];
    const float* WGb = (const float*)d_in[14];

    float* out = (float*)d_out;

    void *pq, *pk, *pv, *pa;
    cudaGetSymbolAddress(&pq, g_q);
    cudaGetSymbolAddress(&pk, g_k);
    cudaGetSymbolAddress(&pv, g_v);
    cudaGetSymbolAddress(&pa, g_att);

    static cudaStream_t s_geo = nullptr;
    static cudaEvent_t  e_fork = nullptr, e_join = nullptr;
    if (s_geo == nullptr) {
        cudaStreamCreateWithFlags(&s_geo, cudaStreamNonBlocking);
        cudaEventCreateWithFlags(&e_fork, cudaEventDisableTiming);
        cudaEventCreateWithFlags(&e_join, cudaEventDisableTiming);
        cudaFuncSetAttribute(attn3,
            cudaFuncAttributeMaxDynamicSharedMemorySize, (int)sizeof(AttnSmem));
    }

    dim3 qkvgrid(GN / 128, GM / 128, 3);    // 384 blocks
    dim3 ogrid  (GN / 128, GM / 64);        // (4, 64) = 256 blocks

    cudaEventRecord(e_fork, 0);
    cudaStreamWaitEvent(s_geo, e_fork, 0);
    geo_bias<<<dim3(NN, BB), 256, 0, s_geo>>>(box, WGw, WGb);
    cudaEventRecord(e_join, s_geo);

    gemm_qkv<<<qkvgrid, 256>>>(xq, xk, xv, Wq, Wk, Wv, bq, bk, bv,
                               (float*)pq, (float*)pk, (float*)pv);

    cudaStreamWaitEvent(0, e_join, 0);

    attn3<<<dim3(NN / 64, HH, BB), 256, sizeof(AttnSmem)>>>(msk);

    gemm_one64<<<ogrid, 256>>>((const float*)pa, Wo, bo, out);
}

// round 13
// speedup vs baseline: 1.2751x; 1.0456x over previous
#include <cuda_runtime.h>
#include <cuda_bf16.h>
#include <mma.h>

using namespace nvcuda;

#define BB 16
#define NN 256
#define DM 512
#define HH 8
#define DK 64

// Scratch (allocation-free rule: __device__ globals)
__device__ float g_q[BB*NN*DM];
__device__ float g_k[BB*NN*DM];
__device__ float g_v[BB*NN*DM];
__device__ float g_bias[BB*HH*NN*NN];   // clamped relu(w_g)
__device__ float g_att[BB*NN*DM];       // attention output pre-Wo

__constant__ float c_dim[8] = {
    1.0f, 0.421696503f, 0.177827941f, 0.0749894209f,
    0.0316227766f, 0.0133352143f, 0.00562341325f, 0.00237137371f};

#define GM 4096
#define GN 512
#define GK 512
#define NKT (GK / 16)   // 32

// convert 8 floats -> hi/lo bf16x2 quads, one 16B STS each
__device__ __forceinline__ void cvt_store8(
    __nv_bfloat16* dst_hi, __nv_bfloat16* dst_lo, const float* v)
{
    __nv_bfloat162 h[4], l[4];
    #pragma unroll
    for (int i = 0; i < 4; i++) {
        float2 f = make_float2(v[2*i], v[2*i + 1]);
        h[i] = __float22bfloat162_rn(f);
        float2 hf = __bfloat1622float2(h[i]);
        l[i] = __float22bfloat162_rn(make_float2(f.x - hf.x, f.y - hf.y));
    }
    *reinterpret_cast<uint4*>(dst_hi) = *reinterpret_cast<const uint4*>(h);
    *reinterpret_cast<uint4*>(dst_lo) = *reinterpret_cast<const uint4*>(l);
}
__device__ __forceinline__ void cvt_store16(
    __nv_bfloat16* dst_hi, __nv_bfloat16* dst_lo, const float* v)
{
    cvt_store8(dst_hi, dst_lo, v);
    cvt_store8(dst_hi + 8, dst_lo + 8, v + 8);
}

// ---------------------------------------------------------------------------
// 64x128 GEMM tile (best measured config) — shared by QKV and output GEMMs.
// C[bm:bm+64, bn:bn+128] = A @ W + bias, bf16 3-term split, double-buffered.
// ---------------------------------------------------------------------------
struct GemmSmem64 {
    __nv_bfloat16 Ah[64][24];
    __nv_bfloat16 Al[64][24];
    __nv_bfloat16 Bh[16][136];
    __nv_bfloat16 Bl[16][136];
};

__device__ __forceinline__ void gemm_tile64(
    GemmSmem64* sm,
    const float* __restrict__ A, const float* __restrict__ W,
    const float* __restrict__ bias, float* __restrict__ C,
    int bm, int bn)
{
    const int tid  = threadIdx.x;
    const int warp = tid >> 5;
    const int lane = tid & 31;
    const int wm   = warp >> 2;     // 0..1 -> rows
    const int wn   = warp & 3;      // 0..3 -> cols

    const int ar = tid >> 1;              // 0..127 (only tid<128 stages A)
    const int ac = (tid & 1) * 8;
    const int br = tid >> 4;
    const int bc = (tid & 15) * 8;
    const bool doA = (tid < 128);

    wmma::fragment<wmma::accumulator, 16, 16, 16, float> acc[2][2];
    #pragma unroll
    for (int i = 0; i < 2; i++)
        #pragma unroll
        for (int j = 0; j < 2; j++)
            wmma::fill_fragment(acc[i][j], 0.0f);

    float va[8], vb[8];
    {
        if (doA) {
            const float* ap = &A[(size_t)(bm + ar) * GK + ac];
            float4 f0 = *reinterpret_cast<const float4*>(ap);
            float4 f1 = *reinterpret_cast<const float4*>(ap + 4);
            va[0]=f0.x; va[1]=f0.y; va[2]=f0.z; va[3]=f0.w;
            va[4]=f1.x; va[5]=f1.y; va[6]=f1.z; va[7]=f1.w;
        }
        const float* bp = &W[(size_t)br * GN + bn + bc];
        float4 g0 = *reinterpret_cast<const float4*>(bp);
        float4 g1 = *reinterpret_cast<const float4*>(bp + 4);
        vb[0]=g0.x; vb[1]=g0.y; vb[2]=g0.z; vb[3]=g0.w;
        vb[4]=g1.x; vb[5]=g1.y; vb[6]=g1.z; vb[7]=g1.w;
        if (doA) cvt_store8(&sm[0].Ah[ar][ac], &sm[0].Al[ar][ac], va);
        cvt_store8(&sm[0].Bh[br][bc], &sm[0].Bl[br][bc], vb);
    }
    __syncthreads();

    for (int kt = 0; kt < NKT; kt++) {
        const int cur = kt & 1;
        const bool more = (kt + 1 < NKT);
        if (more) {
            const int k0 = (kt + 1) * 16;
            if (doA) {
                const float* ap = &A[(size_t)(bm + ar) * GK + k0 + ac];
                float4 f0 = *reinterpret_cast<const float4*>(ap);
                float4 f1 = *reinterpret_cast<const float4*>(ap + 4);
                va[0]=f0.x; va[1]=f0.y; va[2]=f0.z; va[3]=f0.w;
                va[4]=f1.x; va[5]=f1.y; va[6]=f1.z; va[7]=f1.w;
            }
            const float* bp = &W[(size_t)(k0 + br) * GN + bn + bc];
            float4 g0 = *reinterpret_cast<const float4*>(bp);
            float4 g1 = *reinterpret_cast<const float4*>(bp + 4);
            vb[0]=g0.x; vb[1]=g0.y; vb[2]=g0.z; vb[3]=g0.w;
            vb[4]=g1.x; vb[5]=g1.y; vb[6]=g1.z; vb[7]=g1.w;
        }
        {
            GemmSmem64& s = sm[cur];
            wmma::fragment<wmma::matrix_a, 16, 16, 16, __nv_bfloat16,
                           wmma::row_major> ah[2], al[2];
            wmma::fragment<wmma::matrix_b, 16, 16, 16, __nv_bfloat16,
                           wmma::row_major> bh[2], bl[2];
            #pragma unroll
            for (int i = 0; i < 2; i++) {
                wmma::load_matrix_sync(ah[i], &s.Ah[wm * 32 + i * 16][0], 24);
                wmma::load_matrix_sync(al[i], &s.Al[wm * 32 + i * 16][0], 24);
            }
            #pragma unroll
            for (int j = 0; j < 2; j++) {
                wmma::load_matrix_sync(bh[j], &s.Bh[0][wn * 32 + j * 16], 136);
                wmma::load_matrix_sync(bl[j], &s.Bl[0][wn * 32 + j * 16], 136);
            }
            #pragma unroll
            for (int i = 0; i < 2; i++)
                #pragma unroll
                for (int j = 0; j < 2; j++) {
                    wmma::mma_sync(acc[i][j], ah[i], bh[j], acc[i][j]);
                    wmma::mma_sync(acc[i][j], ah[i], bl[j], acc[i][j]);
                    wmma::mma_sync(acc[i][j], al[i], bh[j], acc[i][j]);
                }
        }
        if (more) {
            if (doA) cvt_store8(&sm[cur ^ 1].Ah[ar][ac], &sm[cur ^ 1].Al[ar][ac], va);
            cvt_store8(&sm[cur ^ 1].Bh[br][bc], &sm[cur ^ 1].Bl[br][bc], vb);
        }
        __syncthreads();
    }

    float* epib = reinterpret_cast<float*>(sm) + warp * 288;
    const int er = lane >> 1;
    const int ec = (lane & 1) * 8;
    #pragma unroll
    for (int i = 0; i < 2; i++)
        #pragma unroll
        for (int j = 0; j < 2; j++) {
            wmma::store_matrix_sync(epib, acc[i][j], 18, wmma::mem_row_major);
            __syncwarp();
            const int row = bm + wm * 32 + i * 16 + er;
            const int col = bn + wn * 32 + j * 16 + ec;
            float4 b0 = *reinterpret_cast<const float4*>(&bias[col]);
            float4 b1 = *reinterpret_cast<const float4*>(&bias[col + 4]);
            const float* ep = &epib[er * 18 + ec];
            float4 o0 = {ep[0] + b0.x, ep[1] + b0.y, ep[2] + b0.z, ep[3] + b0.w};
            float4 o1 = {ep[4] + b1.x, ep[5] + b1.y, ep[6] + b1.z, ep[7] + b1.w};
            *reinterpret_cast<float4*>(&C[(size_t)row * GN + col])     = o0;
            *reinterpret_cast<float4*>(&C[(size_t)row * GN + col + 4]) = o1;
            __syncwarp();
        }
}

// QKV: 64x128 tiles, blockIdx.z selects triple. (4,64,3) = 768 blocks.
__global__ __launch_bounds__(256) void gemm_qkv64(
    const float* __restrict__ xq, const float* __restrict__ xk,
    const float* __restrict__ xv,
    const float* __restrict__ Wq, const float* __restrict__ Wk,
    const float* __restrict__ Wv,
    const float* __restrict__ bq, const float* __restrict__ bk,
    const float* __restrict__ bv,
    float* __restrict__ oq, float* __restrict__ ok, float* __restrict__ ov)
{
    __shared__ GemmSmem64 sm[2];
    const float *A, *W, *bias;
    float* C;
    if (blockIdx.z == 0)      { A = xq; W = Wq; bias = bq; C = oq; }
    else if (blockIdx.z == 1) { A = xk; W = Wk; bias = bk; C = ok; }
    else                      { A = xv; W = Wv; bias = bv; C = ov; }
    gemm_tile64(sm, A, W, bias, C, blockIdx.y * 64, blockIdx.x * 128);
}

__global__ __launch_bounds__(256) void gemm_one64(
    const float* __restrict__ A, const float* __restrict__ W,
    const float* __restrict__ bias, float* __restrict__ C)
{
    __shared__ GemmSmem64 sm[2];
    gemm_tile64(sm, A, W, bias, C, blockIdx.y * 64, blockIdx.x * 128);
}

// ---------------------------------------------------------------------------
// Geometric weights (unchanged)
// ---------------------------------------------------------------------------
__global__ __launch_bounds__(256) void geo_bias(
    const float* __restrict__ box, const float* __restrict__ WGw,
    const float* __restrict__ WGb)
{
    __shared__ float sW[HH * 64];
    __shared__ float sB[HH];
    const int b = blockIdx.y;
    const int q = blockIdx.x;
    const int m = threadIdx.x;

    sW[m] = WGw[m];
    sW[m + 256] = WGw[m + 256];
    if (m < HH) sB[m] = WGb[m];
    __syncthreads();

    const float* bq = box + ((size_t)b * NN + q) * 4;
    const float x0q = bq[0], y0q = bq[1], x1q = bq[2], y1q = bq[3];
    const float cxq = (x0q + x1q) * 0.5f, cyq = (y0q + y1q) * 0.5f;
    const float wq = x1q - x0q + 1.0f,   hq = y1q - y0q + 1.0f;

    const float* bmp = box + ((size_t)b * NN + m) * 4;
    const float x0m = bmp[0], y0m = bmp[1], x1m = bmp[2], y1m = bmp[3];
    const float cxm = (x0m + x1m) * 0.5f, cym = (y0m + y1m) * 0.5f;
    const float wm = x1m - x0m + 1.0f,    hm = y1m - y0m + 1.0f;

    float delta[4];
    delta[0] = logf(fmaxf(fabsf((cxq - cxm) / wq), 0.001f));
    delta[1] = logf(fmaxf(fabsf((cyq - cym) / hq), 0.001f));
    delta[2] = logf(wq / wm);
    delta[3] = logf(hq / hm);

    float acc[HH];
    #pragma unroll
    for (int h = 0; h < HH; h++) acc[h] = sB[h];

    #pragma unroll
    for (int p = 0; p < 4; p++) {
        #pragma unroll
        for (int f = 0; f < 8; f++) {
            float ang = 100.0f * delta[p] * c_dim[f];
            float r = ang - 6.28318530717958647692f *
                            rintf(ang * 0.15915494309189533577f);
            float s, c;
            sincosf(r, &s, &c);
            const int idx = p * 8 + f;
            #pragma unroll
            for (int h = 0; h < HH; h++)
                acc[h] += s * sW[h * 64 + idx] + c * sW[h * 64 + 32 + idx];
        }
    }

    #pragma unroll
    for (int h = 0; h < HH; h++) {
        g_bias[(((size_t)b * HH + h) * NN + q) * NN + m] =
            fmaxf(acc[h], 1e-6f);
    }
}

// ---------------------------------------------------------------------------
// Tensor-core attention with ALIASED smem buffers (~91KB -> 2 CTAs/SM):
//   P tiles overwrite K tiles (K dead after scores)
//   Od overwrites S (S dead after softmax)
// ---------------------------------------------------------------------------
struct AttnSmem {
    __nv_bfloat16 Qh[64][72],  Ql[64][72];
    __nv_bfloat16 KPh[64][72], KPl[64][72];   // K tile, then P tile
    __nv_bfloat16 Vh[64][72],  Vl[64][72];
    float SOd[64][68];                        // scores, then Od
    float Os [64][68];
    float M[64], L[64], Sc[64];
};

__global__ __launch_bounds__(256, 2) void attn3(const int* __restrict__ mask)
{
    extern __shared__ char smraw[];
    AttnSmem& sm = *reinterpret_cast<AttnSmem*>(smraw);

    const int qt = blockIdx.x, h = blockIdx.y, b = blockIdx.z;
    const int qb = qt * 64;
    const int tid  = threadIdx.x;
    const int warp = tid >> 5;
    const int wm   = warp >> 2;   // 0..1
    const int wn   = warp & 3;    // 0..3
    const int rq   = tid >> 2;    // 0..63
    const int sub  = tid & 3;
    const int d0   = sub * 16;

    {
        const float* qp = g_q + ((size_t)(b * NN + qb + rq)) * DM + h * DK + d0;
        float v[16];
        #pragma unroll
        for (int g = 0; g < 4; g++) {
            float4 f = *reinterpret_cast<const float4*>(qp + g * 4);
            v[g*4+0] = f.x * 0.125f; v[g*4+1] = f.y * 0.125f;
            v[g*4+2] = f.z * 0.125f; v[g*4+3] = f.w * 0.125f;
        }
        cvt_store16(&sm.Qh[rq][d0], &sm.Ql[rq][d0], v);
    }
    if (tid < 64) { sm.M[tid] = -3.0e38f; sm.L[tid] = 0.0f; }
    #pragma unroll
    for (int j = 0; j < 16; j++) sm.Os[rq][d0 + j] = 0.0f;

    const int* mk = mask + b * NN;
    const float* wgrow = g_bias + ((size_t)(b * HH + h) * NN + qb) * NN + (size_t)rq * NN;

    for (int kt = 0; kt < 4; kt++) {
        const int kg0 = kt * 64;
        __syncthreads();   // protects K restage vs prior PV reads of P
        {
            float v[16];
            const float* kp = g_k + ((size_t)(b * NN + kg0 + rq)) * DM + h * DK + d0;
            #pragma unroll
            for (int g = 0; g < 4; g++) {
                float4 f = *reinterpret_cast<const float4*>(kp + g * 4);
                v[g*4+0]=f.x; v[g*4+1]=f.y; v[g*4+2]=f.z; v[g*4+3]=f.w;
            }
            cvt_store16(&sm.KPh[rq][d0], &sm.KPl[rq][d0], v);
            const float* vp = g_v + ((size_t)(b * NN + kg0 + rq)) * DM + h * DK + d0;
            #pragma unroll
            for (int g = 0; g < 4; g++) {
                float4 f = *reinterpret_cast<const float4*>(vp + g * 4);
                v[g*4+0]=f.x; v[g*4+1]=f.y; v[g*4+2]=f.z; v[g*4+3]=f.w;
            }
            cvt_store16(&sm.Vh[rq][d0], &sm.Vl[rq][d0], v);
        }
        __syncthreads();

        // scores: S = Q·K^T
        {
            wmma::fragment<wmma::accumulator, 16, 16, 16, float> sa[2];
            #pragma unroll
            for (int i = 0; i < 2; i++) wmma::fill_fragment(sa[i], 0.0f);
            #pragma unroll
            for (int kk = 0; kk < 4; kk++) {
                wmma::fragment<wmma::matrix_b, 16, 16, 16, __nv_bfloat16,
                               wmma::col_major> bh, bl;
                wmma::load_matrix_sync(bh, &sm.KPh[wn * 16][kk * 16], 72);
                wmma::load_matrix_sync(bl, &sm.KPl[wn * 16][kk * 16], 72);
                #pragma unroll
                for (int i = 0; i < 2; i++) {
                    wmma::fragment<wmma::matrix_a, 16, 16, 16, __nv_bfloat16,
                                   wmma::row_major> ah, al;
                    wmma::load_matrix_sync(ah, &sm.Qh[wm * 32 + i * 16][kk * 16], 72);
                    wmma::load_matrix_sync(al, &sm.Ql[wm * 32 + i * 16][kk * 16], 72);
                    wmma::mma_sync(sa[i], ah, bh, sa[i]);
                    wmma::mma_sync(sa[i], ah, bl, sa[i]);
                    wmma::mma_sync(sa[i], al, bh, sa[i]);
                }
            }
            #pragma unroll
            for (int i = 0; i < 2; i++)
                wmma::store_matrix_sync(&sm.SOd[wm * 32 + i * 16][wn * 16], sa[i],
                                        68, wmma::mem_row_major);
        }
        __syncthreads();   // scores done -> K region reusable for P

        // online softmax: read S, write P (over K region)
        {
            const int4* mi = reinterpret_cast<const int4*>(&mk[kg0 + d0]);
            int mv[16];
            #pragma unroll
            for (int g = 0; g < 4; g++) {
                int4 m4 = mi[g];
                mv[g*4+0]=m4.x; mv[g*4+1]=m4.y; mv[g*4+2]=m4.z; mv[g*4+3]=m4.w;
            }
            float s[16];
            float mt = -3.0e38f;
            #pragma unroll
            for (int j = 0; j < 16; j++) {
                float sv = sm.SOd[rq][d0 + j];
                if (mv[j] == 0) sv = -1e9f;
                s[j] = sv;
                mt = fmaxf(mt, sv);
            }
            mt = fmaxf(mt, __shfl_xor_sync(0xffffffffu, mt, 1));
            mt = fmaxf(mt, __shfl_xor_sync(0xffffffffu, mt, 2));
            if (sub == 0) {
                float m_old = sm.M[rq];
                float m_new = fmaxf(m_old, mt);
                sm.M[rq] = m_new;
                float sc = __expf(m_old - m_new);
                sm.Sc[rq] = sc;
                sm.L[rq] *= sc;
            }
            __syncwarp();
            const float mq = sm.M[rq];
            float p[16];
            float psum = 0.0f;
            const float* wgp = wgrow + kg0 + d0;
            #pragma unroll
            for (int g = 0; g < 4; g++) {
                float4 w4 = *reinterpret_cast<const float4*>(wgp + g * 4);
                float wv[4] = {w4.x, w4.y, w4.z, w4.w};
                #pragma unroll
                for (int u = 0; u < 4; u++) {
                    float pv = wv[u] * __expf(s[g*4+u] - mq);
                    p[g*4+u] = pv;
                    psum += pv;
                }
            }
            cvt_store16(&sm.KPh[rq][d0], &sm.KPl[rq][d0], p);
            psum += __shfl_xor_sync(0xffffffffu, psum, 1);
            psum += __shfl_xor_sync(0xffffffffu, psum, 2);
            if (sub == 0) sm.L[rq] += psum;
        }
        __syncthreads();   // softmax done -> S region reusable for Od

        // PV: Od = P·V (over S region)
        {
            wmma::fragment<wmma::accumulator, 16, 16, 16, float> pa[2];
            #pragma unroll
            for (int i = 0; i < 2; i++) wmma::fill_fragment(pa[i], 0.0f);
            #pragma unroll
            for (int kk = 0; kk < 4; kk++) {
                wmma::fragment<wmma::matrix_b, 16, 16, 16, __nv_bfloat16,
                               wmma::row_major> bh, bl;
                wmma::load_matrix_sync(bh, &sm.Vh[kk * 16][wn * 16], 72);
                wmma::load_matrix_sync(bl, &sm.Vl[kk * 16][wn * 16], 72);
                #pragma unroll
                for (int i = 0; i < 2; i++) {
                    wmma::fragment<wmma::matrix_a, 16, 16, 16, __nv_bfloat16,
                                   wmma::row_major> ah, al;
                    wmma::load_matrix_sync(ah, &sm.KPh[wm * 32 + i * 16][kk * 16], 72);
                    wmma::load_matrix_sync(al, &sm.KPl[wm * 32 + i * 16][kk * 16], 72);
                    wmma::mma_sync(pa[i], ah, bh, pa[i]);
                    wmma::mma_sync(pa[i], ah, bl, pa[i]);
                    wmma::mma_sync(pa[i], al, bh, pa[i]);
                }
            }
            #pragma unroll
            for (int i = 0; i < 2; i++)
                wmma::store_matrix_sync(&sm.SOd[wm * 32 + i * 16][wn * 16], pa[i],
                                        68, wmma::mem_row_major);
        }
        __syncthreads();

        // merge: Os = Os*scale + Od
        {
            const float sc = sm.Sc[rq];
            #pragma unroll
            for (int j = 0; j < 16; j++)
                sm.Os[rq][d0 + j] = sm.Os[rq][d0 + j] * sc + sm.SOd[rq][d0 + j];
        }
    }
    __syncthreads();

    {
        const float inv = 1.0f / sm.L[rq];
        float* op = g_att + ((size_t)(b * NN + qb + rq)) * DM + h * DK + d0;
        #pragma unroll
        for (int g = 0; g < 4; g++) {
            float4 o;
            o.x = sm.Os[rq][d0 + g*4 + 0] * inv;
            o.y = sm.Os[rq][d0 + g*4 + 1] * inv;
            o.z = sm.Os[rq][d0 + g*4 + 2] * inv;
            o.w = sm.Os[rq][d0 + g*4 + 3] * inv;
            *reinterpret_cast<float4*>(op + g * 4) = o;
        }
    }
}

// ---------------------------------------------------------------------------
extern "C" void kernel_launch(void* const* d_in, const int* in_sizes, int n_in,
                              void* d_out, int out_size)
{
    const float* xq  = (const float*)d_in[0];
    const float* xk  = (const float*)d_in[1];
    const float* xv  = (const float*)d_in[2];
    const float* box = (const float*)d_in[3];
    const int*   msk = (const int*)  d_in[4];
    const float* Wq  = (const float*)d_in[5];
    const float* bq  = (const float*)d_in[6];
    const float* Wk  = (const float*)d_in[7];
    const float* bk  = (const float*)d_in[8];
    const float* Wv  = (const float*)d_in[9];
    const float* bv  = (const float*)d_in[10];
    const float* Wo  = (const float*)d_in[11];
    const float* bo  = (const float*)d_in[12];
    const float* WGw = (const float*)d_in[13];
    const float* WGb = (const float*)d_in[14];

    float* out = (float*)d_out;

    void *pq, *pk, *pv, *pa;
    cudaGetSymbolAddress(&pq, g_q);
    cudaGetSymbolAddress(&pk, g_k);
    cudaGetSymbolAddress(&pv, g_v);
    cudaGetSymbolAddress(&pa, g_att);

    static cudaStream_t s_geo = nullptr;
    static cudaEvent_t  e_fork = nullptr, e_join = nullptr;
    if (s_geo == nullptr) {
        cudaStreamCreateWithFlags(&s_geo, cudaStreamNonBlocking);
        cudaEventCreateWithFlags(&e_fork, cudaEventDisableTiming);
        cudaEventCreateWithFlags(&e_join, cudaEventDisableTiming);
        cudaFuncSetAttribute(attn3,
            cudaFuncAttributeMaxDynamicSharedMemorySize, (int)sizeof(AttnSmem));
    }

    dim3 qkvgrid(GN / 128, GM / 64, 3);     // (4, 64, 3) = 768 blocks
    dim3 ogrid  (GN / 128, GM / 64);        // (4, 64)    = 256 blocks

    cudaEventRecord(e_fork, 0);
    cudaStreamWaitEvent(s_geo, e_fork, 0);
    geo_bias<<<dim3(NN, BB), 256, 0, s_geo>>>(box, WGw, WGb);
    cudaEventRecord(e_join, s_geo);

    gemm_qkv64<<<qkvgrid, 256>>>(xq, xk, xv, Wq, Wk, Wv, bq, bk, bv,
                                 (float*)pq, (float*)pk, (float*)pv);

    cudaStreamWaitEvent(0, e_join, 0);

    attn3<<<dim3(NN / 64, HH, BB), 256, sizeof(AttnSmem)>>>(msk);

    gemm_one64<<<ogrid, 256>>>((const float*)pa, Wo, bo, out);
}